// round 1
// baseline (speedup 1.0000x reference)
#include <cuda_runtime.h>

// Problem constants
#define BB 4
#define NNN 2048
#define CCC 768
#define HHH 12
#define DDD 64
#define MROWS (BB*NNN)     // 8192
#define QKVC (3*CCC)       // 2304
#define BH (BB*HHH)        // 48

// Scratch (device globals — no allocation allowed)
__device__ float g_qkv[MROWS*QKVC];     // [M, 3C]
__device__ float g_q[BH*NNN*DDD];       // [B*H, N, D] (LN'd, scaled)
__device__ float g_k[BH*NNN*DDD];
__device__ float g_v[BH*NNN*DDD];
__device__ float g_att[MROWS*CCC];      // [B, N, C]

// ---------------------------------------------------------------------------
// Tiled fp32 GEMM: C[M,N] = A[M,K] @ B[K,N] (+ bias). 128x128x16 tiles,
// 256 threads, 8x8 per-thread register tile, float4 everywhere.
// Requires M%128==0, N%128==0, K%16==0 (true for all our shapes).
// ---------------------------------------------------------------------------
__global__ __launch_bounds__(256) void sgemm128(
    const float* __restrict__ A, const float* __restrict__ B,
    float* __restrict__ C, int N, int K, const float* __restrict__ bias)
{
    const int BM = 128, BN = 128, BK = 16;
    __shared__ float As[BK][BM];   // transposed A tile
    __shared__ float Bs[BK][BN];

    int tid = threadIdx.x;
    int tr = (tid >> 4) * 8;       // thread row in 128
    int tc = (tid & 15) * 8;       // thread col in 128

    const float* Ablk = A + (size_t)blockIdx.y * BM * K;
    const float* Bblk = B + blockIdx.x * BN;

    float acc[8][8];
#pragma unroll
    for (int i = 0; i < 8; i++)
#pragma unroll
        for (int j = 0; j < 8; j++) acc[i][j] = 0.f;

    for (int k0 = 0; k0 < K; k0 += BK) {
        // Load A tile: 128x16 = 512 float4, 2 per thread, stored transposed
#pragma unroll
        for (int i = 0; i < 2; i++) {
            int idx = tid + i * 256;       // 0..511
            int r = idx >> 2, c4 = idx & 3;
            float4 v = *(const float4*)(Ablk + (size_t)r * K + k0 + c4 * 4);
            As[c4 * 4 + 0][r] = v.x;
            As[c4 * 4 + 1][r] = v.y;
            As[c4 * 4 + 2][r] = v.z;
            As[c4 * 4 + 3][r] = v.w;
        }
        // Load B tile: 16x128 = 512 float4
#pragma unroll
        for (int i = 0; i < 2; i++) {
            int idx = tid + i * 256;
            int r = idx >> 5, c4 = idx & 31;
            *(float4*)(&Bs[r][c4 * 4]) =
                *(const float4*)(Bblk + (size_t)(k0 + r) * N + c4 * 4);
        }
        __syncthreads();

#pragma unroll
        for (int kk = 0; kk < BK; kk++) {
            float a[8], b[8];
            *(float4*)(a)     = *(const float4*)(&As[kk][tr]);
            *(float4*)(a + 4) = *(const float4*)(&As[kk][tr + 4]);
            *(float4*)(b)     = *(const float4*)(&Bs[kk][tc]);
            *(float4*)(b + 4) = *(const float4*)(&Bs[kk][tc + 4]);
#pragma unroll
            for (int i = 0; i < 8; i++)
#pragma unroll
                for (int j = 0; j < 8; j++)
                    acc[i][j] += a[i] * b[j];
        }
        __syncthreads();
    }

    float bv[8] = {0.f, 0.f, 0.f, 0.f, 0.f, 0.f, 0.f, 0.f};
    if (bias) {
        const float* bp = bias + blockIdx.x * BN + tc;
        *(float4*)(bv)     = *(const float4*)(bp);
        *(float4*)(bv + 4) = *(const float4*)(bp + 4);
    }

    float* Cblk = C + (size_t)blockIdx.y * BM * N + blockIdx.x * BN;
#pragma unroll
    for (int i = 0; i < 8; i++) {
#pragma unroll
        for (int j = 0; j < 8; j += 4) {
            float4 v;
            v.x = acc[i][j + 0] + bv[j + 0];
            v.y = acc[i][j + 1] + bv[j + 1];
            v.z = acc[i][j + 2] + bv[j + 2];
            v.w = acc[i][j + 3] + bv[j + 3];
            *(float4*)(Cblk + (size_t)(tr + i) * N + tc + j) = v;
        }
    }
}

// ---------------------------------------------------------------------------
// LayerNorm over D=64 + scatter into [B*H, N, D]. One warp per (row, s, h).
// s=0: q (LN * q_gamma + q_beta, then * D^-0.5); s=1: k (LN); s=2: v (copy).
// ---------------------------------------------------------------------------
__global__ __launch_bounds__(256) void ln_kernel(
    const float* __restrict__ qg, const float* __restrict__ qb,
    const float* __restrict__ kg, const float* __restrict__ kb)
{
    int task = blockIdx.x * 8 + (threadIdx.x >> 5);
    int lane = threadIdx.x & 31;
    int m = task / (3 * HHH);
    int rem = task % (3 * HHH);
    int s = rem / HHH, h = rem % HHH;

    const float* src = g_qkv + (size_t)m * QKVC + s * CCC + h * DDD;
    float x0 = src[lane], x1 = src[lane + 32];

    int b = m >> 11, n = m & (NNN - 1);
    float* dst = (s == 0 ? g_q : (s == 1 ? g_k : g_v))
                 + (((size_t)(b * HHH + h)) * NNN + n) * DDD;

    if (s == 2) { dst[lane] = x0; dst[lane + 32] = x1; return; }

    float sum = x0 + x1, sq = x0 * x0 + x1 * x1;
#pragma unroll
    for (int off = 16; off; off >>= 1) {
        sum += __shfl_xor_sync(0xffffffffu, sum, off);
        sq  += __shfl_xor_sync(0xffffffffu, sq,  off);
    }
    float mean = sum * (1.f / 64.f);
    float var  = sq * (1.f / 64.f) - mean * mean;
    float inv  = rsqrtf(var + 1e-5f);

    const float* g  = (s == 0) ? qg : kg;
    const float* be = (s == 0) ? qb : kb;
    float sc = (s == 0) ? 0.125f : 1.f;   // D^-0.5 = 1/8 folded into q

    dst[lane]      = ((x0 - mean) * inv * g[lane]      + be[lane])      * sc;
    dst[lane + 32] = ((x1 - mean) * inv * g[lane + 32] + be[lane + 32]) * sc;
}

// ---------------------------------------------------------------------------
// Flash attention, fp32. One CTA per (bh, 64-row q tile). 256 threads in a
// 16x16 grid; each thread owns a 4x4 tile of S/P and of O.
// smem: Qs[64][64] (d-major), Xs[64][68] (K tile d-major, then P tile
// row-major, padded to kill PV bank conflicts), Vs[64][64].
// ---------------------------------------------------------------------------
#define FLASH_SMEM ((64*64 + 64*68 + 64*64) * 4)

__global__ __launch_bounds__(256) void flash_kernel()
{
    extern __shared__ float smem[];
    float (*Qs)[64] = (float(*)[64])(smem);
    float (*Xs)[68] = (float(*)[68])(smem + 64 * 64);
    float (*Vs)[64] = (float(*)[64])(smem + 64 * 64 + 64 * 68);

    int bh = blockIdx.y;
    int qt = blockIdx.x;
    int tid = threadIdx.x;
    int ty = tid >> 4, tx = tid & 15;
    int i0 = ty * 4;     // S/O row base
    int c0 = tx * 4;     // S col base (kv idx) == O col base (head dim)

    const float* Qg = g_q + ((size_t)bh * NNN + qt * 64) * DDD;
    const float* Kg = g_k + (size_t)bh * NNN * DDD;
    const float* Vg = g_v + (size_t)bh * NNN * DDD;

    // Load Q tile transposed into Qs[d][i]
    {
        int i = tid >> 2, d0 = (tid & 3) * 16;
#pragma unroll
        for (int t = 0; t < 16; t += 4) {
            float4 v = *(const float4*)(Qg + (size_t)i * DDD + d0 + t);
            Qs[d0 + t + 0][i] = v.x;
            Qs[d0 + t + 1][i] = v.y;
            Qs[d0 + t + 2][i] = v.z;
            Qs[d0 + t + 3][i] = v.w;
        }
    }

    float o[4][4];
    float m[4], l[4];
#pragma unroll
    for (int r = 0; r < 4; r++) {
        m[r] = -1e30f; l[r] = 0.f;
#pragma unroll
        for (int c = 0; c < 4; c++) o[r][c] = 0.f;
    }

    for (int kt = 0; kt < NNN / 64; kt++) {
        __syncthreads();   // protects Xs/Vs reuse (and Qs on first iter)
        // Load K tile transposed into Xs[d][j], V tile into Vs[j][c]
        {
            int j = tid >> 2, d0 = (tid & 3) * 16;
            const float* kr = Kg + (size_t)(kt * 64 + j) * DDD + d0;
            const float* vr = Vg + (size_t)(kt * 64 + j) * DDD + d0;
#pragma unroll
            for (int t = 0; t < 16; t += 4) {
                float4 kv = *(const float4*)(kr + t);
                Xs[d0 + t + 0][j] = kv.x;
                Xs[d0 + t + 1][j] = kv.y;
                Xs[d0 + t + 2][j] = kv.z;
                Xs[d0 + t + 3][j] = kv.w;
                *(float4*)(&Vs[j][d0 + t]) = *(const float4*)(vr + t);
            }
        }
        __syncthreads();

        // S tile = Q K^T (each thread 4x4)
        float s[4][4];
#pragma unroll
        for (int r = 0; r < 4; r++)
#pragma unroll
            for (int c = 0; c < 4; c++) s[r][c] = 0.f;
#pragma unroll
        for (int d = 0; d < DDD; d++) {
            float a[4], b[4];
            *(float4*)a = *(const float4*)(&Qs[d][i0]);
            *(float4*)b = *(const float4*)(&Xs[d][c0]);
#pragma unroll
            for (int r = 0; r < 4; r++)
#pragma unroll
                for (int c = 0; c < 4; c++)
                    s[r][c] += a[r] * b[c];
        }

        // Row max across the 16-lane tx group
        float mt[4];
#pragma unroll
        for (int r = 0; r < 4; r++)
            mt[r] = fmaxf(fmaxf(s[r][0], s[r][1]), fmaxf(s[r][2], s[r][3]));
#pragma unroll
        for (int off = 1; off < 16; off <<= 1)
#pragma unroll
            for (int r = 0; r < 4; r++)
                mt[r] = fmaxf(mt[r], __shfl_xor_sync(0xffffffffu, mt[r], off));

        float alpha[4];
#pragma unroll
        for (int r = 0; r < 4; r++) {
            float mn = fmaxf(m[r], mt[r]);
            alpha[r] = __expf(m[r] - mn);
            m[r] = mn;
        }

        // exp + row sum
        float rs[4] = {0.f, 0.f, 0.f, 0.f};
#pragma unroll
        for (int r = 0; r < 4; r++)
#pragma unroll
            for (int c = 0; c < 4; c++) {
                s[r][c] = __expf(s[r][c] - m[r]);
                rs[r] += s[r][c];
            }
#pragma unroll
        for (int off = 1; off < 16; off <<= 1)
#pragma unroll
            for (int r = 0; r < 4; r++)
                rs[r] += __shfl_xor_sync(0xffffffffu, rs[r], off);
#pragma unroll
        for (int r = 0; r < 4; r++) {
            l[r] = l[r] * alpha[r] + rs[r];
#pragma unroll
            for (int c = 0; c < 4; c++) o[r][c] *= alpha[r];
        }

        __syncthreads();   // done reading Xs as K
        // Store P tile into Xs[i][j] (row-major, padded rows)
#pragma unroll
        for (int r = 0; r < 4; r++)
#pragma unroll
            for (int c = 0; c < 4; c++)
                Xs[i0 + r][c0 + c] = s[r][c];
        __syncthreads();

        // O += P @ V
#pragma unroll
        for (int j = 0; j < 64; j++) {
            float b[4];
            *(float4*)b = *(const float4*)(&Vs[j][c0]);
            float a0 = Xs[i0 + 0][j];
            float a1 = Xs[i0 + 1][j];
            float a2 = Xs[i0 + 2][j];
            float a3 = Xs[i0 + 3][j];
#pragma unroll
            for (int c = 0; c < 4; c++) {
                o[0][c] += a0 * b[c];
                o[1][c] += a1 * b[c];
                o[2][c] += a2 * b[c];
                o[3][c] += a3 * b[c];
            }
        }
    }

    // Epilogue: normalize and write to g_att in [B, N, C] layout
    int b = bh / HHH, h = bh % HHH;
    float* outp = g_att + ((size_t)(b * NNN) + qt * 64) * CCC + h * DDD;
#pragma unroll
    for (int r = 0; r < 4; r++) {
        float inv = 1.f / l[r];
        float4 v;
        v.x = o[r][0] * inv; v.y = o[r][1] * inv;
        v.z = o[r][2] * inv; v.w = o[r][3] * inv;
        *(float4*)(outp + (size_t)(i0 + r) * CCC + c0) = v;
    }
}

// ---------------------------------------------------------------------------
extern "C" void kernel_launch(void* const* d_in, const int* in_sizes, int n_in,
                              void* d_out, int out_size)
{
    const float* x       = (const float*)d_in[0];
    const float* w_qkv   = (const float*)d_in[1];
    const float* q_gamma = (const float*)d_in[2];
    const float* q_beta  = (const float*)d_in[3];
    const float* k_gamma = (const float*)d_in[4];
    const float* k_beta  = (const float*)d_in[5];
    const float* w_proj  = (const float*)d_in[6];
    const float* b_proj  = (const float*)d_in[7];
    float* out = (float*)d_out;

    float *qkv_p, *att_p;
    cudaGetSymbolAddress((void**)&qkv_p, g_qkv);
    cudaGetSymbolAddress((void**)&att_p, g_att);

    static bool attr_set = false;
    if (!attr_set) {
        cudaFuncSetAttribute(flash_kernel,
                             cudaFuncAttributeMaxDynamicSharedMemorySize,
                             FLASH_SMEM);
        attr_set = true;
    }

    // 1) QKV GEMM: [8192, 768] @ [768, 2304]
    sgemm128<<<dim3(QKVC / 128, MROWS / 128), 256>>>(
        x, w_qkv, qkv_p, QKVC, CCC, nullptr);

    // 2) LayerNorm + reshape to [B*H, N, D]
    ln_kernel<<<(MROWS * 3 * HHH) / 8, 256>>>(q_gamma, q_beta, k_gamma, k_beta);

    // 3) Flash attention
    flash_kernel<<<dim3(NNN / 64, BH), 256, FLASH_SMEM>>>();

    // 4) Output projection: [8192, 768] @ [768, 768] + bias
    sgemm128<<<dim3(CCC / 128, MROWS / 128), 256>>>(
        att_p, w_proj, out, CCC, CCC, b_proj);
}

// round 4
// speedup vs baseline: 2.2667x; 2.2667x over previous
#include <cuda_runtime.h>
#include <cuda_bf16.h>
#include <cstdint>

// Problem constants
#define BB 4
#define NNN 2048
#define CCC 768
#define HHH 12
#define DDD 64
#define MROWS (BB*NNN)     // 8192
#define QKVC (3*CCC)       // 2304
#define BH (BB*HHH)        // 48

// Scratch (device globals — no allocation allowed)
__device__ float g_qkv[MROWS*QKVC];          // [M, 3C] fp32
// bf16 hi/lo planes for q,k,v: [B*H, N, D] as u32 (32 u32 = 64 bf16 per row)
__device__ unsigned g_qh[BH*NNN*32], g_ql[BH*NNN*32];
__device__ unsigned g_kh[BH*NNN*32], g_kl[BH*NNN*32];
__device__ unsigned g_vh[BH*NNN*32], g_vl[BH*NNN*32];
__device__ float g_att[MROWS*CCC];           // [B, N, C] fp32

// ---------------------------------------------------------------------------
// helpers
// ---------------------------------------------------------------------------
__device__ __forceinline__ void mma_bf16(float* d, const unsigned* a,
                                         unsigned b0, unsigned b1)
{
    asm volatile(
        "mma.sync.aligned.m16n8k16.row.col.f32.bf16.bf16.f32 "
        "{%0,%1,%2,%3}, {%4,%5,%6,%7}, {%8,%9}, {%0,%1,%2,%3};\n"
        : "+f"(d[0]), "+f"(d[1]), "+f"(d[2]), "+f"(d[3])
        : "r"(a[0]), "r"(a[1]), "r"(a[2]), "r"(a[3]), "r"(b0), "r"(b1));
}

__device__ __forceinline__ void ldsm_x2_trans(unsigned& r0, unsigned& r1,
                                              unsigned addr)
{
    asm volatile(
        "ldmatrix.sync.aligned.m8n8.x2.trans.shared.b16 {%0,%1}, [%2];"
        : "=r"(r0), "=r"(r1) : "r"(addr));
}

// Split (x,y) into packed bf16x2 hi + lo residual (low 16 bits = x).
__device__ __forceinline__ void split2(float x, float y,
                                       unsigned& h, unsigned& l)
{
    __nv_bfloat162 hb = __floats2bfloat162_rn(x, y);
    float2 hf = __bfloat1622float2(hb);
    __nv_bfloat162 lb = __floats2bfloat162_rn(x - hf.x, y - hf.y);
    h = *reinterpret_cast<unsigned*>(&hb);
    l = *reinterpret_cast<unsigned*>(&lb);
}

// ---------------------------------------------------------------------------
// bf16x3 GEMM: C[M,N] = A[M,K] @ B[K,N] (+bias), fp32 in/out.
// 128x128x16 block, 8 warps (4x2), warp tile 32x64.
// A smem: [m][k] bf16 pairs, row stride 12 u32 (24 bf16) -> conflict-free
// b32 fragment loads. B smem: [k][n] rows, stride 68 u32 (272B == 4 banks
// mod 32) -> conflict-free ldmatrix.x2.trans.
// ---------------------------------------------------------------------------
__global__ __launch_bounds__(256) void tgemm_bf16(
    const float* __restrict__ A, const float* __restrict__ B,
    float* __restrict__ C, int N, int K, const float* __restrict__ bias)
{
    __shared__ unsigned Ash[128 * 12], Asl[128 * 12];
    __shared__ unsigned Bsh[16 * 68],  Bsl[16 * 68];

    int tid = threadIdx.x, w = tid >> 5, lane = tid & 31;
    int g = lane >> 2, q4 = lane & 3;
    int wm = w >> 1, wn = w & 1;

    const float* Ab = A + (size_t)blockIdx.y * 128 * K;
    const float* Bb = B + blockIdx.x * 128;

    unsigned bsh_addr = (unsigned)__cvta_generic_to_shared(Bsh)
                        + (lane & 15) * 272;
    unsigned bsl_addr = (unsigned)__cvta_generic_to_shared(Bsl)
                        + (lane & 15) * 272;

    float acc[2][8][4];
#pragma unroll
    for (int mt = 0; mt < 2; mt++)
#pragma unroll
        for (int nt = 0; nt < 8; nt++)
#pragma unroll
            for (int e = 0; e < 4; e++) acc[mt][nt][e] = 0.f;

    for (int k0 = 0; k0 < K; k0 += 16) {
        __syncthreads();
        // A tile: 128x16 fp32 -> hi/lo bf16 pairs along k. 1024 float2.
#pragma unroll
        for (int i = 0; i < 4; i++) {
            int idx = tid + i * 256;
            int r = idx >> 3, c2 = idx & 7;
            float2 v = *(const float2*)(Ab + (size_t)r * K + k0 + 2 * c2);
            split2(v.x, v.y, Ash[r * 12 + c2], Asl[r * 12 + c2]);
        }
        // B tile: 16x128 fp32 -> hi/lo bf16, [k][n]. 1024 float2.
#pragma unroll
        for (int i = 0; i < 4; i++) {
            int idx = tid + i * 256;
            int r = idx >> 6, c2 = idx & 63;
            float2 v = *(const float2*)(Bb + (size_t)(k0 + r) * N + 2 * c2);
            split2(v.x, v.y, Bsh[r * 68 + c2], Bsl[r * 68 + c2]);
        }
        __syncthreads();

        unsigned ah[2][4], al[2][4];
#pragma unroll
        for (int mt = 0; mt < 2; mt++) {
            int row = wm * 32 + mt * 16;
            ah[mt][0] = Ash[(row + g) * 12 + q4];
            ah[mt][1] = Ash[(row + 8 + g) * 12 + q4];
            ah[mt][2] = Ash[(row + g) * 12 + q4 + 4];
            ah[mt][3] = Ash[(row + 8 + g) * 12 + q4 + 4];
            al[mt][0] = Asl[(row + g) * 12 + q4];
            al[mt][1] = Asl[(row + 8 + g) * 12 + q4];
            al[mt][2] = Asl[(row + g) * 12 + q4 + 4];
            al[mt][3] = Asl[(row + 8 + g) * 12 + q4 + 4];
        }
#pragma unroll
        for (int nt = 0; nt < 8; nt++) {
            int colb = (wn * 64 + nt * 8) * 2;   // byte offset along n
            unsigned bh0, bh1, bl0, bl1;
            ldsm_x2_trans(bh0, bh1, bsh_addr + colb);
            ldsm_x2_trans(bl0, bl1, bsl_addr + colb);
#pragma unroll
            for (int mt = 0; mt < 2; mt++) {
                mma_bf16(acc[mt][nt], ah[mt], bh0, bh1);
                mma_bf16(acc[mt][nt], ah[mt], bl0, bl1);
                mma_bf16(acc[mt][nt], al[mt], bh0, bh1);
            }
        }
    }

    int row = blockIdx.y * 128 + wm * 32 + g;
    int colb = blockIdx.x * 128 + wn * 64;
#pragma unroll
    for (int nt = 0; nt < 8; nt++) {
        int col = colb + nt * 8 + 2 * q4;
        float bv0 = 0.f, bv1 = 0.f;
        if (bias) { bv0 = bias[col]; bv1 = bias[col + 1]; }
#pragma unroll
        for (int mt = 0; mt < 2; mt++) {
            float2 u0, u1;
            u0.x = acc[mt][nt][0] + bv0; u0.y = acc[mt][nt][1] + bv1;
            u1.x = acc[mt][nt][2] + bv0; u1.y = acc[mt][nt][3] + bv1;
            *(float2*)(C + (size_t)(row + mt * 16) * N + col) = u0;
            *(float2*)(C + (size_t)(row + mt * 16 + 8) * N + col) = u1;
        }
    }
}

// ---------------------------------------------------------------------------
// LayerNorm over D=64 + split to bf16 hi/lo planes in [B*H, N, D].
// One warp per (row, s, h); lane owns dims 2*lane, 2*lane+1.
// ---------------------------------------------------------------------------
__global__ __launch_bounds__(256) void ln_kernel(
    const float* __restrict__ qg, const float* __restrict__ qb,
    const float* __restrict__ kg, const float* __restrict__ kb)
{
    int task = blockIdx.x * 8 + (threadIdx.x >> 5);
    int lane = threadIdx.x & 31;
    int m = task / (3 * HHH);
    int rem = task % (3 * HHH);
    int s = rem / HHH, h = rem % HHH;

    float2 x = *(const float2*)(g_qkv + (size_t)m * QKVC + s * CCC
                                + h * DDD + 2 * lane);

    int b = m >> 11, n = m & (NNN - 1);
    size_t idx = (((size_t)(b * HHH + h)) * NNN + n) * 32 + lane;

    if (s == 2) {
        unsigned hv, lv;
        split2(x.x, x.y, hv, lv);
        g_vh[idx] = hv; g_vl[idx] = lv;
        return;
    }

    float sum = x.x + x.y, sq = x.x * x.x + x.y * x.y;
#pragma unroll
    for (int off = 16; off; off >>= 1) {
        sum += __shfl_xor_sync(0xffffffffu, sum, off);
        sq  += __shfl_xor_sync(0xffffffffu, sq,  off);
    }
    float mean = sum * (1.f / 64.f);
    float var  = sq * (1.f / 64.f) - mean * mean;
    float inv  = rsqrtf(var + 1e-5f);

    const float* gw = (s == 0) ? qg : kg;
    const float* be = (s == 0) ? qb : kb;
    float2 gv = *(const float2*)(gw + 2 * lane);
    float2 bv = *(const float2*)(be + 2 * lane);
    float sc = (s == 0) ? 0.125f : 1.f;   // D^-0.5 folded into q

    float y0 = ((x.x - mean) * inv * gv.x + bv.x) * sc;
    float y1 = ((x.y - mean) * inv * gv.y + bv.y) * sc;
    unsigned hv, lv;
    split2(y0, y1, hv, lv);
    if (s == 0) { g_qh[idx] = hv; g_ql[idx] = lv; }
    else        { g_kh[idx] = hv; g_kl[idx] = lv; }
}

// ---------------------------------------------------------------------------
// Flash attention, bf16x3 MMA. CTA = 128 q rows of one head, 8 warps x 16
// rows, KV tile 64. Q/K frags: direct b32 LDS (stride 36 u32 -> bank 4g+q,
// conflict-free). V: ldmatrix.x2.trans (144B rows, conflict-free). The S
// C-fragment layout equals the P A-fragment layout for bf16 k16 MMA, so no
// shuffles: P is packed+split in registers.
// smem u32 words: Qh|Ql (128*36 each) Kh|Kl (64*36) Vh|Vl (64*36) = 73728B.
// ---------------------------------------------------------------------------
#define FL_WORDS (128*36*2 + 64*36*4)
#define FL_SMEM  (FL_WORDS*4)

__global__ __launch_bounds__(256) void flash_bf16()
{
    extern __shared__ unsigned sm[];
    unsigned* Qh = sm;
    unsigned* Ql = Qh + 128 * 36;
    unsigned* Kh = Ql + 128 * 36;
    unsigned* Kl = Kh + 64 * 36;
    unsigned* Vh = Kl + 64 * 36;
    unsigned* Vl = Vh + 64 * 36;

    int bh = blockIdx.y, qt = blockIdx.x;
    int tid = threadIdx.x, w = tid >> 5, lane = tid & 31;
    int g = lane >> 2, q4 = lane & 3;

    const unsigned* gqh = g_qh + ((size_t)bh * NNN + qt * 128) * 32;
    const unsigned* gql = g_ql + ((size_t)bh * NNN + qt * 128) * 32;

    // Q fill: 1024 uint4 per plane
#pragma unroll
    for (int i = 0; i < 4; i++) {
        int idx = tid + i * 256;
        int r = idx >> 3, c4 = (idx & 7) * 4;
        *(uint4*)(Qh + r * 36 + c4) = *(const uint4*)(gqh + r * 32 + c4);
        *(uint4*)(Ql + r * 36 + c4) = *(const uint4*)(gql + r * 32 + c4);
    }

    unsigned vh_base = (unsigned)__cvta_generic_to_shared(Vh);
    unsigned vl_base = (unsigned)__cvta_generic_to_shared(Vl);

    float O[8][4];
    float m0 = -1e30f, m1 = -1e30f, l0 = 0.f, l1 = 0.f;
#pragma unroll
    for (int dt = 0; dt < 8; dt++)
#pragma unroll
        for (int e = 0; e < 4; e++) O[dt][e] = 0.f;

    const unsigned* Qwh = Qh + (w * 16) * 36;
    const unsigned* Qwl = Ql + (w * 16) * 36;

    for (int kt = 0; kt < NNN / 64; kt++) {
        const unsigned* gkh = g_kh + ((size_t)bh * NNN + kt * 64) * 32;
        const unsigned* gkl = g_kl + ((size_t)bh * NNN + kt * 64) * 32;
        const unsigned* gvh = g_vh + ((size_t)bh * NNN + kt * 64) * 32;
        const unsigned* gvl = g_vl + ((size_t)bh * NNN + kt * 64) * 32;
        __syncthreads();
#pragma unroll
        for (int i = 0; i < 2; i++) {
            int idx = tid + i * 256;
            int r = idx >> 3, c4 = (idx & 7) * 4;
            *(uint4*)(Kh + r * 36 + c4) = *(const uint4*)(gkh + r * 32 + c4);
            *(uint4*)(Kl + r * 36 + c4) = *(const uint4*)(gkl + r * 32 + c4);
            *(uint4*)(Vh + r * 36 + c4) = *(const uint4*)(gvh + r * 32 + c4);
            *(uint4*)(Vl + r * 36 + c4) = *(const uint4*)(gvl + r * 32 + c4);
        }
        __syncthreads();

        // S = Q K^T
        float S[8][4];
#pragma unroll
        for (int n = 0; n < 8; n++)
#pragma unroll
            for (int e = 0; e < 4; e++) S[n][e] = 0.f;

#pragma unroll
        for (int kk = 0; kk < 4; kk++) {
            int base = kk * 8 + q4;
            unsigned ah[4], al[4];
            ah[0] = Qwh[g * 36 + base];       ah[1] = Qwh[(g + 8) * 36 + base];
            ah[2] = Qwh[g * 36 + base + 4];   ah[3] = Qwh[(g + 8) * 36 + base + 4];
            al[0] = Qwl[g * 36 + base];       al[1] = Qwl[(g + 8) * 36 + base];
            al[2] = Qwl[g * 36 + base + 4];   al[3] = Qwl[(g + 8) * 36 + base + 4];
#pragma unroll
            for (int nt = 0; nt < 8; nt++) {
                int rw = (nt * 8 + g) * 36;
                unsigned bh0 = Kh[rw + base], bh1 = Kh[rw + base + 4];
                unsigned bl0 = Kl[rw + base], bl1 = Kl[rw + base + 4];
                mma_bf16(S[nt], ah, bh0, bh1);
                mma_bf16(S[nt], ah, bl0, bl1);
                mma_bf16(S[nt], al, bh0, bh1);
            }
        }

        // Online softmax. c0/c1 -> row g ; c2/c3 -> row g+8.
        float mt0 = -1e30f, mt1 = -1e30f;
#pragma unroll
        for (int n = 0; n < 8; n++) {
            mt0 = fmaxf(mt0, fmaxf(S[n][0], S[n][1]));
            mt1 = fmaxf(mt1, fmaxf(S[n][2], S[n][3]));
        }
        mt0 = fmaxf(mt0, __shfl_xor_sync(0xffffffffu, mt0, 1));
        mt0 = fmaxf(mt0, __shfl_xor_sync(0xffffffffu, mt0, 2));
        mt1 = fmaxf(mt1, __shfl_xor_sync(0xffffffffu, mt1, 1));
        mt1 = fmaxf(mt1, __shfl_xor_sync(0xffffffffu, mt1, 2));

        float mn0 = fmaxf(m0, mt0), mn1 = fmaxf(m1, mt1);
        float al0 = __expf(m0 - mn0), al1 = __expf(m1 - mn1);
        m0 = mn0; m1 = mn1;

        float rs0 = 0.f, rs1 = 0.f;
#pragma unroll
        for (int n = 0; n < 8; n++) {
            S[n][0] = __expf(S[n][0] - mn0); rs0 += S[n][0];
            S[n][1] = __expf(S[n][1] - mn0); rs0 += S[n][1];
            S[n][2] = __expf(S[n][2] - mn1); rs1 += S[n][2];
            S[n][3] = __expf(S[n][3] - mn1); rs1 += S[n][3];
        }
        rs0 += __shfl_xor_sync(0xffffffffu, rs0, 1);
        rs0 += __shfl_xor_sync(0xffffffffu, rs0, 2);
        rs1 += __shfl_xor_sync(0xffffffffu, rs1, 1);
        rs1 += __shfl_xor_sync(0xffffffffu, rs1, 2);

        l0 = l0 * al0 + rs0;
        l1 = l1 * al1 + rs1;
#pragma unroll
        for (int dt = 0; dt < 8; dt++) {
            O[dt][0] *= al0; O[dt][1] *= al0;
            O[dt][2] *= al1; O[dt][3] *= al1;
        }

        // P: C-frag == A-frag; pack + split in registers.
        unsigned Ph[8][2], Pl[8][2];
#pragma unroll
        for (int n = 0; n < 8; n++) {
            split2(S[n][0], S[n][1], Ph[n][0], Pl[n][0]);
            split2(S[n][2], S[n][3], Ph[n][1], Pl[n][1]);
        }

        // O += P @ V
#pragma unroll
        for (int ks = 0; ks < 4; ks++) {
            unsigned ah[4] = {Ph[2*ks][0], Ph[2*ks][1],
                              Ph[2*ks+1][0], Ph[2*ks+1][1]};
            unsigned al_[4] = {Pl[2*ks][0], Pl[2*ks][1],
                               Pl[2*ks+1][0], Pl[2*ks+1][1]};
            unsigned rowoff = (ks * 16 + (lane & 15)) * 144;
#pragma unroll
            for (int dt = 0; dt < 8; dt++) {
                unsigned vh0, vh1, vl0, vl1;
                ldsm_x2_trans(vh0, vh1, vh_base + rowoff + dt * 16);
                ldsm_x2_trans(vl0, vl1, vl_base + rowoff + dt * 16);
                mma_bf16(O[dt], ah, vh0, vh1);
                mma_bf16(O[dt], ah, vl0, vl1);
                mma_bf16(O[dt], al_, vh0, vh1);
            }
        }
    }

    // Epilogue -> g_att [B, N, C]
    int b = bh / HHH, h = bh % HHH;
    int row0 = qt * 128 + w * 16 + g;
    float inv0 = 1.f / l0, inv1 = 1.f / l1;
    float* base = g_att + ((size_t)b * NNN + row0) * CCC + h * DDD;
#pragma unroll
    for (int dt = 0; dt < 8; dt++) {
        float2 u0, u1;
        u0.x = O[dt][0] * inv0; u0.y = O[dt][1] * inv0;
        u1.x = O[dt][2] * inv1; u1.y = O[dt][3] * inv1;
        *(float2*)(base + dt * 8 + 2 * q4) = u0;
        *(float2*)(base + (size_t)8 * CCC + dt * 8 + 2 * q4) = u1;
    }
}

// ---------------------------------------------------------------------------
extern "C" void kernel_launch(void* const* d_in, const int* in_sizes, int n_in,
                              void* d_out, int out_size)
{
    const float* x       = (const float*)d_in[0];
    const float* w_qkv   = (const float*)d_in[1];
    const float* q_gamma = (const float*)d_in[2];
    const float* q_beta  = (const float*)d_in[3];
    const float* k_gamma = (const float*)d_in[4];
    const float* k_beta  = (const float*)d_in[5];
    const float* w_proj  = (const float*)d_in[6];
    const float* b_proj  = (const float*)d_in[7];
    float* out = (float*)d_out;

    float *qkv_p, *att_p;
    cudaGetSymbolAddress((void**)&qkv_p, g_qkv);
    cudaGetSymbolAddress((void**)&att_p, g_att);

    cudaFuncSetAttribute(flash_bf16,
                         cudaFuncAttributeMaxDynamicSharedMemorySize, FL_SMEM);

    // 1) QKV GEMM: [8192, 768] @ [768, 2304]
    tgemm_bf16<<<dim3(QKVC / 128, MROWS / 128), 256>>>(
        x, w_qkv, qkv_p, QKVC, CCC, nullptr);

    // 2) LayerNorm + split to bf16 hi/lo planes [B*H, N, D]
    ln_kernel<<<(MROWS * 3 * HHH) / 8, 256>>>(q_gamma, q_beta, k_gamma, k_beta);

    // 3) Flash attention (bf16x3 MMA)
    flash_bf16<<<dim3(NNN / 128, BH), 256, FL_SMEM>>>();

    // 4) Output projection: [8192, 768] @ [768, 768] + bias
    tgemm_bf16<<<dim3(CCC / 128, MROWS / 128), 256>>>(
        att_p, w_proj, out, CCC, CCC, b_proj);
}

// round 5
// speedup vs baseline: 2.5456x; 1.1230x over previous
#include <cuda_runtime.h>
#include <cuda_bf16.h>
#include <cstdint>

// Problem constants
#define BB 4
#define NNN 2048
#define CCC 768
#define HHH 12
#define DDD 64
#define MROWS (BB*NNN)     // 8192
#define QKVC (3*CCC)       // 2304
#define BH (BB*HHH)        // 48
#define CW (CCC/2)         // 384 u32 words per row of C
#define QKVW (QKVC/2)      // 1152

// Scratch (device globals — no allocation allowed)
__device__ float g_qkv[MROWS*QKVC];                  // [M, 3C] fp32
// bf16 hi/lo planes (u32 = packed bf16x2 along the contiguous dim)
__device__ unsigned g_xh[MROWS*CW],  g_xl[MROWS*CW];     // x      [M, C]
__device__ unsigned g_w1h[CCC*QKVW], g_w1l[CCC*QKVW];    // w_qkv  [K, 3C]
__device__ unsigned g_w2h[CCC*CW],   g_w2l[CCC*CW];      // w_proj [K, C]
__device__ unsigned g_qh[BH*NNN*32], g_ql[BH*NNN*32];    // q [B*H,N,D]
__device__ unsigned g_kh[BH*NNN*32], g_kl[BH*NNN*32];
__device__ unsigned g_vh[BH*NNN*32], g_vl[BH*NNN*32];
__device__ unsigned g_ah[MROWS*CW],  g_al[MROWS*CW];     // attn out [M, C]

// ---------------------------------------------------------------------------
// helpers
// ---------------------------------------------------------------------------
__device__ __forceinline__ void mma_bf16(float* d, const unsigned* a,
                                         unsigned b0, unsigned b1)
{
    asm volatile(
        "mma.sync.aligned.m16n8k16.row.col.f32.bf16.bf16.f32 "
        "{%0,%1,%2,%3}, {%4,%5,%6,%7}, {%8,%9}, {%0,%1,%2,%3};\n"
        : "+f"(d[0]), "+f"(d[1]), "+f"(d[2]), "+f"(d[3])
        : "r"(a[0]), "r"(a[1]), "r"(a[2]), "r"(a[3]), "r"(b0), "r"(b1));
}

__device__ __forceinline__ void ldsm_x2_trans(unsigned& r0, unsigned& r1,
                                              unsigned addr)
{
    asm volatile(
        "ldmatrix.sync.aligned.m8n8.x2.trans.shared.b16 {%0,%1}, [%2];"
        : "=r"(r0), "=r"(r1) : "r"(addr));
}

__device__ __forceinline__ void cp16(unsigned dst, const void* src)
{
    asm volatile("cp.async.cg.shared.global [%0], [%1], 16;"
                 :: "r"(dst), "l"(src));
}
__device__ __forceinline__ void cp_commit()
{
    asm volatile("cp.async.commit_group;");
}
template <int N>
__device__ __forceinline__ void cp_wait()
{
    asm volatile("cp.async.wait_group %0;" :: "n"(N));
}

// Split (x,y) into packed bf16x2 hi + lo residual (low 16 bits = x).
__device__ __forceinline__ void split2(float x, float y,
                                       unsigned& h, unsigned& l)
{
    __nv_bfloat162 hb = __floats2bfloat162_rn(x, y);
    float2 hf = __bfloat1622float2(hb);
    __nv_bfloat162 lb = __floats2bfloat162_rn(x - hf.x, y - hf.y);
    h = *reinterpret_cast<unsigned*>(&hb);
    l = *reinterpret_cast<unsigned*>(&lb);
}

// ---------------------------------------------------------------------------
// fp32 -> bf16 hi/lo plane conversion (pair-wise)
// ---------------------------------------------------------------------------
__global__ __launch_bounds__(256) void split_kernel(
    const float* __restrict__ src, unsigned* __restrict__ h,
    unsigned* __restrict__ l, int npairs)
{
    int i = blockIdx.x * 256 + threadIdx.x;
    if (i < npairs) {
        float2 v = reinterpret_cast<const float2*>(src)[i];
        split2(v.x, v.y, h[i], l[i]);
    }
}

// ---------------------------------------------------------------------------
// bf16x3 GEMM v2: C[M,N] = A[M,K] @ B[K,N] (+bias), bf16-plane in, fp32 out
// (or skipped if C==nullptr semantics not needed). 128x128x32 block, 8 warps
// (4x2), cp.async 2-stage double buffer.
// A plane smem: [128][20] u32 per plane (stride 20 -> banks 20r+c all
// distinct). B plane smem: [32][68] u32 (272B rows -> conflict-free
// ldmatrix.x2.trans).
// Dynamic smem u32 words: A 2buf*2pl*2560=10240; B 2buf*2pl*2176=8704.
// ---------------------------------------------------------------------------
#define GA_PL 2560              // 128*20
#define GA_BUF (2*GA_PL)        // 5120
#define GB_PL 2176              // 32*68
#define GB_BUF (2*GB_PL)        // 4352
#define GB_BASE (2*GA_BUF)      // 10240
#define GEMM_WORDS (GB_BASE + 2*GB_BUF)   // 18944
#define GEMM_SMEM (GEMM_WORDS*4)          // 75776 B

__global__ __launch_bounds__(256) void tgemm_v2(
    const unsigned* __restrict__ Ah, const unsigned* __restrict__ Al,
    const unsigned* __restrict__ Bh, const unsigned* __restrict__ Bl,
    float* __restrict__ C, int N, int K, const float* __restrict__ bias)
{
    extern __shared__ unsigned sm[];
    const int Kw = K >> 1, Nw = N >> 1;
    const int nsteps = K / 32;

    int tid = threadIdx.x, w = tid >> 5, lane = tid & 31;
    int g = lane >> 2, q4 = lane & 3;
    int wm = w >> 1, wn = w & 1;

    unsigned smbase = (unsigned)__cvta_generic_to_shared(sm);
    size_t arow0 = (size_t)blockIdx.y * 128;
    int bcol0 = blockIdx.x * 64;          // in u32 pairs

    const unsigned* Apl[2] = {Ah, Al};
    const unsigned* Bpl[2] = {Bh, Bl};

    // prefetch lambda-ish macro: step s into buffer b
    auto prefetch = [&](int s, int b) {
        int kp0 = s * 16;                 // k offset in pairs
        // A: 1024 chunks (2 planes x 128 rows x 4)
#pragma unroll
        for (int i = 0; i < 4; i++) {
            int idx = tid + i * 256;
            int p = idx >> 9, rem = idx & 511;
            int r = rem >> 2, c = rem & 3;
            unsigned dst = smbase + (b * GA_BUF + p * GA_PL + r * 20 + c * 4) * 4;
            cp16(dst, Apl[p] + (arow0 + r) * Kw + kp0 + c * 4);
        }
        // B: 1024 chunks (2 planes x 32 rows x 16)
#pragma unroll
        for (int i = 0; i < 4; i++) {
            int idx = tid + i * 256;
            int p = idx >> 9, rem = idx & 511;
            int r = rem >> 4, c = rem & 15;
            unsigned dst = smbase + (GB_BASE + b * GB_BUF + p * GB_PL
                                     + r * 68 + c * 4) * 4;
            cp16(dst, Bpl[p] + (size_t)(s * 32 + r) * Nw + bcol0 + c * 4);
        }
        cp_commit();
    };

    float acc[2][8][4];
#pragma unroll
    for (int mt = 0; mt < 2; mt++)
#pragma unroll
        for (int nt = 0; nt < 8; nt++)
#pragma unroll
            for (int e = 0; e < 4; e++) acc[mt][nt][e] = 0.f;

    prefetch(0, 0);

    for (int s = 0; s < nsteps; s++) {
        int b = s & 1;
        if (s + 1 < nsteps) { prefetch(s + 1, b ^ 1); cp_wait<1>(); }
        else                { cp_wait<0>(); }
        __syncthreads();

        const unsigned* Ash = sm + b * GA_BUF;
        const unsigned* Asl = Ash + GA_PL;
        unsigned bh_addr = smbase + (GB_BASE + b * GB_BUF) * 4
                           + (lane & 15) * 272;
        unsigned bl_addr = bh_addr + GB_PL * 4;

#pragma unroll
        for (int kc = 0; kc < 2; kc++) {
            unsigned ah[2][4], al[2][4];
#pragma unroll
            for (int mt = 0; mt < 2; mt++) {
                int r0 = (wm * 32 + mt * 16 + g) * 20;
                int r1 = (wm * 32 + mt * 16 + 8 + g) * 20;
                int cidx = kc * 8 + q4;
                ah[mt][0] = Ash[r0 + cidx];     ah[mt][1] = Ash[r1 + cidx];
                ah[mt][2] = Ash[r0 + cidx + 4]; ah[mt][3] = Ash[r1 + cidx + 4];
                al[mt][0] = Asl[r0 + cidx];     al[mt][1] = Asl[r1 + cidx];
                al[mt][2] = Asl[r0 + cidx + 4]; al[mt][3] = Asl[r1 + cidx + 4];
            }
            unsigned rowb = kc * 16 * 272;
#pragma unroll
            for (int nt = 0; nt < 8; nt++) {
                int colb = (wn * 64 + nt * 8) * 2;
                unsigned bh0, bh1, bl0, bl1;
                ldsm_x2_trans(bh0, bh1, bh_addr + rowb + colb);
                ldsm_x2_trans(bl0, bl1, bl_addr + rowb + colb);
#pragma unroll
                for (int mt = 0; mt < 2; mt++) {
                    mma_bf16(acc[mt][nt], ah[mt], bh0, bh1);
                    mma_bf16(acc[mt][nt], ah[mt], bl0, bl1);
                    mma_bf16(acc[mt][nt], al[mt], bh0, bh1);
                }
            }
        }
        __syncthreads();
    }

    int row = blockIdx.y * 128 + wm * 32 + g;
    int colb = blockIdx.x * 128 + wn * 64;
#pragma unroll
    for (int nt = 0; nt < 8; nt++) {
        int col = colb + nt * 8 + 2 * q4;
        float bv0 = 0.f, bv1 = 0.f;
        if (bias) { bv0 = bias[col]; bv1 = bias[col + 1]; }
#pragma unroll
        for (int mt = 0; mt < 2; mt++) {
            float2 u0, u1;
            u0.x = acc[mt][nt][0] + bv0; u0.y = acc[mt][nt][1] + bv1;
            u1.x = acc[mt][nt][2] + bv0; u1.y = acc[mt][nt][3] + bv1;
            *(float2*)(C + (size_t)(row + mt * 16) * N + col) = u0;
            *(float2*)(C + (size_t)(row + mt * 16 + 8) * N + col) = u1;
        }
    }
}

// ---------------------------------------------------------------------------
// LayerNorm over D=64 + split to bf16 hi/lo planes in [B*H, N, D].
// ---------------------------------------------------------------------------
__global__ __launch_bounds__(256) void ln_kernel(
    const float* __restrict__ qg, const float* __restrict__ qb,
    const float* __restrict__ kg, const float* __restrict__ kb)
{
    int task = blockIdx.x * 8 + (threadIdx.x >> 5);
    int lane = threadIdx.x & 31;
    int m = task / (3 * HHH);
    int rem = task % (3 * HHH);
    int s = rem / HHH, h = rem % HHH;

    float2 x = *(const float2*)(g_qkv + (size_t)m * QKVC + s * CCC
                                + h * DDD + 2 * lane);

    int b = m >> 11, n = m & (NNN - 1);
    size_t idx = (((size_t)(b * HHH + h)) * NNN + n) * 32 + lane;

    if (s == 2) {
        unsigned hv, lv;
        split2(x.x, x.y, hv, lv);
        g_vh[idx] = hv; g_vl[idx] = lv;
        return;
    }

    float sum = x.x + x.y, sq = x.x * x.x + x.y * x.y;
#pragma unroll
    for (int off = 16; off; off >>= 1) {
        sum += __shfl_xor_sync(0xffffffffu, sum, off);
        sq  += __shfl_xor_sync(0xffffffffu, sq,  off);
    }
    float mean = sum * (1.f / 64.f);
    float var  = sq * (1.f / 64.f) - mean * mean;
    float inv  = rsqrtf(var + 1e-5f);

    const float* gw = (s == 0) ? qg : kg;
    const float* be = (s == 0) ? qb : kb;
    float2 gv = *(const float2*)(gw + 2 * lane);
    float2 bv = *(const float2*)(be + 2 * lane);
    float sc = (s == 0) ? 0.125f : 1.f;

    float y0 = ((x.x - mean) * inv * gv.x + bv.x) * sc;
    float y1 = ((x.y - mean) * inv * gv.y + bv.y) * sc;
    unsigned hv, lv;
    split2(y0, y1, hv, lv);
    if (s == 0) { g_qh[idx] = hv; g_ql[idx] = lv; }
    else        { g_kh[idx] = hv; g_kl[idx] = lv; }
}

// ---------------------------------------------------------------------------
// Flash attention v2: bf16x3, Q frags in registers (loaded once), K/V tiles
// cp.async double-buffered. CTA = 128 q rows x 1 head, 8 warps x 16 rows,
// KV tile 64. Epilogue writes bf16 hi/lo att planes (consumed by proj GEMM).
// smem u32: [2 buf][4 planes: Kh Kl Vh Vl][64*36] = 18432 words = 73728 B.
// ---------------------------------------------------------------------------
#define FV_PL 2304              // 64*36
#define FV_BUF (4*FV_PL)        // 9216
#define FL_WORDS (2*FV_BUF)
#define FL_SMEM (FL_WORDS*4)    // 73728

__global__ __launch_bounds__(256) void flash_v2()
{
    extern __shared__ unsigned sm[];
    unsigned smbase = (unsigned)__cvta_generic_to_shared(sm);

    int bh = blockIdx.y, qt = blockIdx.x;
    int tid = threadIdx.x, w = tid >> 5, lane = tid & 31;
    int g = lane >> 2, q4 = lane & 3;

    // Q fragments from global planes (loop-invariant): rows w*16+g, +8.
    unsigned qfh[4][4], qfl[4][4];
    {
        const unsigned* r0h = g_qh + ((size_t)bh * NNN + qt * 128 + w * 16 + g) * 32;
        const unsigned* r1h = r0h + 8 * 32;
        const unsigned* r0l = g_ql + ((size_t)bh * NNN + qt * 128 + w * 16 + g) * 32;
        const unsigned* r1l = r0l + 8 * 32;
#pragma unroll
        for (int kk = 0; kk < 4; kk++) {
            int c = kk * 8 + q4;
            qfh[kk][0] = r0h[c];     qfh[kk][1] = r1h[c];
            qfh[kk][2] = r0h[c + 4]; qfh[kk][3] = r1h[c + 4];
            qfl[kk][0] = r0l[c];     qfl[kk][1] = r1l[c];
            qfl[kk][2] = r0l[c + 4]; qfl[kk][3] = r1l[c + 4];
        }
    }

    const unsigned* pl[4] = {
        g_kh + (size_t)bh * NNN * 32, g_kl + (size_t)bh * NNN * 32,
        g_vh + (size_t)bh * NNN * 32, g_vl + (size_t)bh * NNN * 32};

    auto prefetch = [&](int kt, int b) {
        // 2048 chunks: 4 planes x 64 rows x 8
#pragma unroll
        for (int i = 0; i < 8; i++) {
            int idx = tid + i * 256;
            int p = idx >> 9, rem = idx & 511;
            int r = rem >> 3, c = rem & 7;
            unsigned dst = smbase + (b * FV_BUF + p * FV_PL + r * 36 + c * 4) * 4;
            cp16(dst, pl[p] + (size_t)(kt * 64 + r) * 32 + c * 4);
        }
        cp_commit();
    };

    float O[8][4];
    float m0 = -1e30f, m1 = -1e30f, l0 = 0.f, l1 = 0.f;
#pragma unroll
    for (int dt = 0; dt < 8; dt++)
#pragma unroll
        for (int e = 0; e < 4; e++) O[dt][e] = 0.f;

    prefetch(0, 0);

    for (int kt = 0; kt < NNN / 64; kt++) {
        int b = kt & 1;
        if (kt + 1 < NNN / 64) { prefetch(kt + 1, b ^ 1); cp_wait<1>(); }
        else                   { cp_wait<0>(); }
        __syncthreads();

        const unsigned* Kh = sm + b * FV_BUF;
        const unsigned* Kl = Kh + FV_PL;
        unsigned vh_base = smbase + (b * FV_BUF + 2 * FV_PL) * 4;
        unsigned vl_base = vh_base + FV_PL * 4;

        // S = Q K^T
        float S[8][4];
#pragma unroll
        for (int n = 0; n < 8; n++)
#pragma unroll
            for (int e = 0; e < 4; e++) S[n][e] = 0.f;

#pragma unroll
        for (int kk = 0; kk < 4; kk++) {
            int base = kk * 8 + q4;
#pragma unroll
            for (int nt = 0; nt < 8; nt++) {
                int rw = (nt * 8 + g) * 36;
                unsigned bh0 = Kh[rw + base], bh1 = Kh[rw + base + 4];
                unsigned bl0 = Kl[rw + base], bl1 = Kl[rw + base + 4];
                mma_bf16(S[nt], qfh[kk], bh0, bh1);
                mma_bf16(S[nt], qfh[kk], bl0, bl1);
                mma_bf16(S[nt], qfl[kk], bh0, bh1);
            }
        }

        // Online softmax. c0/c1 -> row g ; c2/c3 -> row g+8.
        float mt0 = -1e30f, mt1 = -1e30f;
#pragma unroll
        for (int n = 0; n < 8; n++) {
            mt0 = fmaxf(mt0, fmaxf(S[n][0], S[n][1]));
            mt1 = fmaxf(mt1, fmaxf(S[n][2], S[n][3]));
        }
        mt0 = fmaxf(mt0, __shfl_xor_sync(0xffffffffu, mt0, 1));
        mt0 = fmaxf(mt0, __shfl_xor_sync(0xffffffffu, mt0, 2));
        mt1 = fmaxf(mt1, __shfl_xor_sync(0xffffffffu, mt1, 1));
        mt1 = fmaxf(mt1, __shfl_xor_sync(0xffffffffu, mt1, 2));

        float mn0 = fmaxf(m0, mt0), mn1 = fmaxf(m1, mt1);
        float al0 = __expf(m0 - mn0), al1 = __expf(m1 - mn1);
        m0 = mn0; m1 = mn1;

        float rs0 = 0.f, rs1 = 0.f;
#pragma unroll
        for (int n = 0; n < 8; n++) {
            S[n][0] = __expf(S[n][0] - mn0); rs0 += S[n][0];
            S[n][1] = __expf(S[n][1] - mn0); rs0 += S[n][1];
            S[n][2] = __expf(S[n][2] - mn1); rs1 += S[n][2];
            S[n][3] = __expf(S[n][3] - mn1); rs1 += S[n][3];
        }
        rs0 += __shfl_xor_sync(0xffffffffu, rs0, 1);
        rs0 += __shfl_xor_sync(0xffffffffu, rs0, 2);
        rs1 += __shfl_xor_sync(0xffffffffu, rs1, 1);
        rs1 += __shfl_xor_sync(0xffffffffu, rs1, 2);

        l0 = l0 * al0 + rs0;
        l1 = l1 * al1 + rs1;
#pragma unroll
        for (int dt = 0; dt < 8; dt++) {
            O[dt][0] *= al0; O[dt][1] *= al0;
            O[dt][2] *= al1; O[dt][3] *= al1;
        }

        // P: C-frag == A-frag; pack + split in registers.
        unsigned Ph[8][2], Pl[8][2];
#pragma unroll
        for (int n = 0; n < 8; n++) {
            split2(S[n][0], S[n][1], Ph[n][0], Pl[n][0]);
            split2(S[n][2], S[n][3], Ph[n][1], Pl[n][1]);
        }

        // O += P @ V
#pragma unroll
        for (int ks = 0; ks < 4; ks++) {
            unsigned ah[4] = {Ph[2*ks][0], Ph[2*ks][1],
                              Ph[2*ks+1][0], Ph[2*ks+1][1]};
            unsigned al_[4] = {Pl[2*ks][0], Pl[2*ks][1],
                               Pl[2*ks+1][0], Pl[2*ks+1][1]};
            unsigned rowoff = (ks * 16 + (lane & 15)) * 144;
#pragma unroll
            for (int dt = 0; dt < 8; dt++) {
                unsigned vh0, vh1, vl0, vl1;
                ldsm_x2_trans(vh0, vh1, vh_base + rowoff + dt * 16);
                ldsm_x2_trans(vl0, vl1, vl_base + rowoff + dt * 16);
                mma_bf16(O[dt], ah, vh0, vh1);
                mma_bf16(O[dt], ah, vl0, vl1);
                mma_bf16(O[dt], al_, vh0, vh1);
            }
        }
        __syncthreads();   // all warps done with buf b before it's refilled
    }

    // Epilogue -> bf16 hi/lo att planes [M, C] (u32 pairs)
    int b2 = bh / HHH, h = bh % HHH;
    int row0 = qt * 128 + w * 16 + g;
    float inv0 = 1.f / l0, inv1 = 1.f / l1;
    size_t base0 = (size_t)(b2 * NNN + row0) * CW + h * 32;
    size_t base1 = base0 + (size_t)8 * CW;
#pragma unroll
    for (int dt = 0; dt < 8; dt++) {
        unsigned hv, lv;
        split2(O[dt][0] * inv0, O[dt][1] * inv0, hv, lv);
        g_ah[base0 + dt * 4 + q4] = hv; g_al[base0 + dt * 4 + q4] = lv;
        split2(O[dt][2] * inv1, O[dt][3] * inv1, hv, lv);
        g_ah[base1 + dt * 4 + q4] = hv; g_al[base1 + dt * 4 + q4] = lv;
    }
}

// ---------------------------------------------------------------------------
extern "C" void kernel_launch(void* const* d_in, const int* in_sizes, int n_in,
                              void* d_out, int out_size)
{
    const float* x       = (const float*)d_in[0];
    const float* w_qkv   = (const float*)d_in[1];
    const float* q_gamma = (const float*)d_in[2];
    const float* q_beta  = (const float*)d_in[3];
    const float* k_gamma = (const float*)d_in[4];
    const float* k_beta  = (const float*)d_in[5];
    const float* w_proj  = (const float*)d_in[6];
    const float* b_proj  = (const float*)d_in[7];
    float* out = (float*)d_out;

    float* qkv_p;
    unsigned *xh, *xl, *w1h, *w1l, *w2h, *w2l, *ah, *al;
    cudaGetSymbolAddress((void**)&qkv_p, g_qkv);
    cudaGetSymbolAddress((void**)&xh,  g_xh);  cudaGetSymbolAddress((void**)&xl,  g_xl);
    cudaGetSymbolAddress((void**)&w1h, g_w1h); cudaGetSymbolAddress((void**)&w1l, g_w1l);
    cudaGetSymbolAddress((void**)&w2h, g_w2h); cudaGetSymbolAddress((void**)&w2l, g_w2l);
    cudaGetSymbolAddress((void**)&ah,  g_ah);  cudaGetSymbolAddress((void**)&al,  g_al);

    cudaFuncSetAttribute(tgemm_v2,
                         cudaFuncAttributeMaxDynamicSharedMemorySize, GEMM_SMEM);
    cudaFuncSetAttribute(flash_v2,
                         cudaFuncAttributeMaxDynamicSharedMemorySize, FL_SMEM);

    // 0) fp32 -> bf16 hi/lo planes
    split_kernel<<<(MROWS*CW + 255) / 256, 256>>>(x, xh, xl, MROWS*CW);
    split_kernel<<<(CCC*QKVW + 255) / 256, 256>>>(w_qkv, w1h, w1l, CCC*QKVW);
    split_kernel<<<(CCC*CW + 255) / 256, 256>>>(w_proj, w2h, w2l, CCC*CW);

    // 1) QKV GEMM: [8192, 768] @ [768, 2304] -> fp32 g_qkv
    tgemm_v2<<<dim3(QKVC / 128, MROWS / 128), 256, GEMM_SMEM>>>(
        xh, xl, w1h, w1l, qkv_p, QKVC, CCC, nullptr);

    // 2) LayerNorm + split to bf16 hi/lo planes [B*H, N, D]
    ln_kernel<<<(MROWS * 3 * HHH) / 8, 256>>>(q_gamma, q_beta, k_gamma, k_beta);

    // 3) Flash attention (bf16x3, pipelined) -> att planes
    flash_v2<<<dim3(NNN / 128, BH), 256, FL_SMEM>>>();

    // 4) Output projection: [8192, 768] @ [768, 768] + bias -> out
    tgemm_v2<<<dim3(CCC / 128, MROWS / 128), 256, GEMM_SMEM>>>(
        ah, al, w2h, w2l, out, CCC, CCC, b_proj);
}

// round 6
// speedup vs baseline: 2.9424x; 1.1559x over previous
#include <cuda_runtime.h>
#include <cuda_bf16.h>
#include <cstdint>

// Problem constants
#define BB 4
#define NNN 2048
#define CCC 768
#define HHH 12
#define DDD 64
#define MROWS (BB*NNN)     // 8192
#define QKVC (3*CCC)       // 2304
#define BH (BB*HHH)        // 48
#define CW (CCC/2)         // 384 u32 words per row of C
#define QKVW (QKVC/2)      // 1152

// Scratch (device globals — no allocation allowed)
__device__ float g_qkv[MROWS*QKVC];                  // [M, 3C] fp32
// bf16 hi/lo planes (u32 = packed bf16x2 along the contiguous dim)
__device__ unsigned g_xh[MROWS*CW],  g_xl[MROWS*CW];     // x      [M, C]
__device__ unsigned g_w1h[CCC*QKVW], g_w1l[CCC*QKVW];    // w_qkv  [K, 3C]
__device__ unsigned g_w2h[CCC*CW],   g_w2l[CCC*CW];      // w_proj [K, C]
__device__ unsigned g_qh[BH*NNN*32], g_ql[BH*NNN*32];    // q [B*H,N,D]
__device__ unsigned g_kh[BH*NNN*32], g_kl[BH*NNN*32];
__device__ unsigned g_vh[BH*NNN*32], g_vl[BH*NNN*32];
__device__ unsigned g_ah[MROWS*CW],  g_al[MROWS*CW];     // attn out [M, C]

// ---------------------------------------------------------------------------
// helpers
// ---------------------------------------------------------------------------
__device__ __forceinline__ void mma_bf16(float* d, const unsigned* a,
                                         unsigned b0, unsigned b1)
{
    asm volatile(
        "mma.sync.aligned.m16n8k16.row.col.f32.bf16.bf16.f32 "
        "{%0,%1,%2,%3}, {%4,%5,%6,%7}, {%8,%9}, {%0,%1,%2,%3};\n"
        : "+f"(d[0]), "+f"(d[1]), "+f"(d[2]), "+f"(d[3])
        : "r"(a[0]), "r"(a[1]), "r"(a[2]), "r"(a[3]), "r"(b0), "r"(b1));
}

__device__ __forceinline__ void ldsm_x2_trans(unsigned& r0, unsigned& r1,
                                              unsigned addr)
{
    asm volatile(
        "ldmatrix.sync.aligned.m8n8.x2.trans.shared.b16 {%0,%1}, [%2];"
        : "=r"(r0), "=r"(r1) : "r"(addr));
}

__device__ __forceinline__ void cp16(unsigned dst, const void* src)
{
    asm volatile("cp.async.cg.shared.global [%0], [%1], 16;"
                 :: "r"(dst), "l"(src));
}
__device__ __forceinline__ void cp_commit()
{
    asm volatile("cp.async.commit_group;");
}
template <int N>
__device__ __forceinline__ void cp_wait()
{
    asm volatile("cp.async.wait_group %0;" :: "n"(N));
}

// Split (x,y) into packed bf16x2 hi + lo residual (low 16 bits = x).
__device__ __forceinline__ void split2(float x, float y,
                                       unsigned& h, unsigned& l)
{
    __nv_bfloat162 hb = __floats2bfloat162_rn(x, y);
    float2 hf = __bfloat1622float2(hb);
    __nv_bfloat162 lb = __floats2bfloat162_rn(x - hf.x, y - hf.y);
    h = *reinterpret_cast<unsigned*>(&hb);
    l = *reinterpret_cast<unsigned*>(&lb);
}

// ---------------------------------------------------------------------------
// fp32 -> bf16 hi/lo plane conversion (pair-wise)
// ---------------------------------------------------------------------------
__global__ __launch_bounds__(256) void split_kernel(
    const float* __restrict__ src, unsigned* __restrict__ h,
    unsigned* __restrict__ l, int npairs)
{
    int i = blockIdx.x * 256 + threadIdx.x;
    if (i < npairs) {
        float2 v = reinterpret_cast<const float2*>(src)[i];
        split2(v.x, v.y, h[i], l[i]);
    }
}

// ---------------------------------------------------------------------------
// bf16x3 GEMM v2 (unchanged from round 5): 128x128x32 block, 8 warps,
// cp.async 2-stage double buffer.
// ---------------------------------------------------------------------------
#define GA_PL 2560              // 128*20
#define GA_BUF (2*GA_PL)        // 5120
#define GB_PL 2176              // 32*68
#define GB_BUF (2*GB_PL)        // 4352
#define GB_BASE (2*GA_BUF)      // 10240
#define GEMM_WORDS (GB_BASE + 2*GB_BUF)   // 18944
#define GEMM_SMEM (GEMM_WORDS*4)          // 75776 B

__global__ __launch_bounds__(256) void tgemm_v2(
    const unsigned* __restrict__ Ah, const unsigned* __restrict__ Al,
    const unsigned* __restrict__ Bh, const unsigned* __restrict__ Bl,
    float* __restrict__ C, int N, int K, const float* __restrict__ bias)
{
    extern __shared__ unsigned sm[];
    const int Kw = K >> 1, Nw = N >> 1;
    const int nsteps = K / 32;

    int tid = threadIdx.x, w = tid >> 5, lane = tid & 31;
    int g = lane >> 2, q4 = lane & 3;
    int wm = w >> 1, wn = w & 1;

    unsigned smbase = (unsigned)__cvta_generic_to_shared(sm);
    size_t arow0 = (size_t)blockIdx.y * 128;
    int bcol0 = blockIdx.x * 64;          // in u32 pairs

    const unsigned* Apl[2] = {Ah, Al};
    const unsigned* Bpl[2] = {Bh, Bl};

    auto prefetch = [&](int s, int b) {
        int kp0 = s * 16;                 // k offset in pairs
#pragma unroll
        for (int i = 0; i < 4; i++) {
            int idx = tid + i * 256;
            int p = idx >> 9, rem = idx & 511;
            int r = rem >> 2, c = rem & 3;
            unsigned dst = smbase + (b * GA_BUF + p * GA_PL + r * 20 + c * 4) * 4;
            cp16(dst, Apl[p] + (arow0 + r) * Kw + kp0 + c * 4);
        }
#pragma unroll
        for (int i = 0; i < 4; i++) {
            int idx = tid + i * 256;
            int p = idx >> 9, rem = idx & 511;
            int r = rem >> 4, c = rem & 15;
            unsigned dst = smbase + (GB_BASE + b * GB_BUF + p * GB_PL
                                     + r * 68 + c * 4) * 4;
            cp16(dst, Bpl[p] + (size_t)(s * 32 + r) * Nw + bcol0 + c * 4);
        }
        cp_commit();
    };

    float acc[2][8][4];
#pragma unroll
    for (int mt = 0; mt < 2; mt++)
#pragma unroll
        for (int nt = 0; nt < 8; nt++)
#pragma unroll
            for (int e = 0; e < 4; e++) acc[mt][nt][e] = 0.f;

    prefetch(0, 0);

    for (int s = 0; s < nsteps; s++) {
        int b = s & 1;
        if (s + 1 < nsteps) { prefetch(s + 1, b ^ 1); cp_wait<1>(); }
        else                { cp_wait<0>(); }
        __syncthreads();

        const unsigned* Ash = sm + b * GA_BUF;
        const unsigned* Asl = Ash + GA_PL;
        unsigned bh_addr = smbase + (GB_BASE + b * GB_BUF) * 4
                           + (lane & 15) * 272;
        unsigned bl_addr = bh_addr + GB_PL * 4;

#pragma unroll
        for (int kc = 0; kc < 2; kc++) {
            unsigned ah[2][4], al[2][4];
#pragma unroll
            for (int mt = 0; mt < 2; mt++) {
                int r0 = (wm * 32 + mt * 16 + g) * 20;
                int r1 = (wm * 32 + mt * 16 + 8 + g) * 20;
                int cidx = kc * 8 + q4;
                ah[mt][0] = Ash[r0 + cidx];     ah[mt][1] = Ash[r1 + cidx];
                ah[mt][2] = Ash[r0 + cidx + 4]; ah[mt][3] = Ash[r1 + cidx + 4];
                al[mt][0] = Asl[r0 + cidx];     al[mt][1] = Asl[r1 + cidx];
                al[mt][2] = Asl[r0 + cidx + 4]; al[mt][3] = Asl[r1 + cidx + 4];
            }
            unsigned rowb = kc * 16 * 272;
#pragma unroll
            for (int nt = 0; nt < 8; nt++) {
                int colb = (wn * 64 + nt * 8) * 2;
                unsigned bh0, bh1, bl0, bl1;
                ldsm_x2_trans(bh0, bh1, bh_addr + rowb + colb);
                ldsm_x2_trans(bl0, bl1, bl_addr + rowb + colb);
#pragma unroll
                for (int mt = 0; mt < 2; mt++) {
                    mma_bf16(acc[mt][nt], ah[mt], bh0, bh1);
                    mma_bf16(acc[mt][nt], ah[mt], bl0, bl1);
                    mma_bf16(acc[mt][nt], al[mt], bh0, bh1);
                }
            }
        }
        __syncthreads();
    }

    int row = blockIdx.y * 128 + wm * 32 + g;
    int colb = blockIdx.x * 128 + wn * 64;
#pragma unroll
    for (int nt = 0; nt < 8; nt++) {
        int col = colb + nt * 8 + 2 * q4;
        float bv0 = 0.f, bv1 = 0.f;
        if (bias) { bv0 = bias[col]; bv1 = bias[col + 1]; }
#pragma unroll
        for (int mt = 0; mt < 2; mt++) {
            float2 u0, u1;
            u0.x = acc[mt][nt][0] + bv0; u0.y = acc[mt][nt][1] + bv1;
            u1.x = acc[mt][nt][2] + bv0; u1.y = acc[mt][nt][3] + bv1;
            *(float2*)(C + (size_t)(row + mt * 16) * N + col) = u0;
            *(float2*)(C + (size_t)(row + mt * 16 + 8) * N + col) = u1;
        }
    }
}

// ---------------------------------------------------------------------------
// LayerNorm over D=64 + split to bf16 hi/lo planes in [B*H, N, D].
// ---------------------------------------------------------------------------
__global__ __launch_bounds__(256) void ln_kernel(
    const float* __restrict__ qg, const float* __restrict__ qb,
    const float* __restrict__ kg, const float* __restrict__ kb)
{
    int task = blockIdx.x * 8 + (threadIdx.x >> 5);
    int lane = threadIdx.x & 31;
    int m = task / (3 * HHH);
    int rem = task % (3 * HHH);
    int s = rem / HHH, h = rem % HHH;

    float2 x = *(const float2*)(g_qkv + (size_t)m * QKVC + s * CCC
                                + h * DDD + 2 * lane);

    int b = m >> 11, n = m & (NNN - 1);
    size_t idx = (((size_t)(b * HHH + h)) * NNN + n) * 32 + lane;

    if (s == 2) {
        unsigned hv, lv;
        split2(x.x, x.y, hv, lv);
        g_vh[idx] = hv; g_vl[idx] = lv;
        return;
    }

    float sum = x.x + x.y, sq = x.x * x.x + x.y * x.y;
#pragma unroll
    for (int off = 16; off; off >>= 1) {
        sum += __shfl_xor_sync(0xffffffffu, sum, off);
        sq  += __shfl_xor_sync(0xffffffffu, sq,  off);
    }
    float mean = sum * (1.f / 64.f);
    float var  = sq * (1.f / 64.f) - mean * mean;
    float inv  = rsqrtf(var + 1e-5f);

    const float* gw = (s == 0) ? qg : kg;
    const float* be = (s == 0) ? qb : kb;
    float2 gv = *(const float2*)(gw + 2 * lane);
    float2 bv = *(const float2*)(be + 2 * lane);
    float sc = (s == 0) ? 0.125f : 1.f;

    float y0 = ((x.x - mean) * inv * gv.x + bv.x) * sc;
    float y1 = ((x.y - mean) * inv * gv.y + bv.y) * sc;
    unsigned hv, lv;
    split2(y0, y1, hv, lv);
    if (s == 0) { g_qh[idx] = hv; g_ql[idx] = lv; }
    else        { g_kh[idx] = hv; g_kl[idx] = lv; }
}

// ---------------------------------------------------------------------------
// Flash attention v3: bf16x3, 2 CTAs/SM. Q planes in smem (loaded once via
// cp.async, fragments re-read per iteration). K/V double-buffered cp.async.
// Inline P split (no persistent P arrays) -> ~110 live regs, fits
// __launch_bounds__(256,2). smem: Q 2*128*36 + KV 2buf*4pl*64*36 = 27648
// words = 110592 B/CTA -> 2 CTAs = 216 KB/SM.
// ---------------------------------------------------------------------------
#define FQ_PL 4608              // 128*36
#define FQ_TOT (2*FQ_PL)        // 9216
#define FV_PL 2304              // 64*36
#define FV_BUF (4*FV_PL)        // 9216
#define FL_WORDS (FQ_TOT + 2*FV_BUF)      // 27648
#define FL_SMEM (FL_WORDS*4)              // 110592

__global__ __launch_bounds__(256, 2) void flash_v3()
{
    extern __shared__ unsigned sm[];
    unsigned smbase = (unsigned)__cvta_generic_to_shared(sm);

    int bh = blockIdx.y, qt = blockIdx.x;
    int tid = threadIdx.x, w = tid >> 5, lane = tid & 31;
    int g = lane >> 2, q4 = lane & 3;

    // Q fill (once): 2 planes x 128 rows x 8 16B-chunks = 1024 chunks
    {
        const unsigned* gq[2] = {
            g_qh + ((size_t)bh * NNN + qt * 128) * 32,
            g_ql + ((size_t)bh * NNN + qt * 128) * 32};
#pragma unroll
        for (int i = 0; i < 4; i++) {
            int idx = tid + i * 256;
            int p = idx >> 9, rem = idx & 511;
            int r = rem >> 2, c = rem & 3;           // c: 4B-chunk of 16B? no:
            // 512 chunks per plane: r(128) x c(4 chunks of 16B = 16 words? )
            // row = 32 words = 8 chunks -> need r(128)*c(4)? 128*4=512 ✓ but
            // 4 chunks * 4 words = 16 words != 32. Use 2 loops of 8 chunks:
            (void)p; (void)r; (void)c;
        }
        // simpler: 2048 chunks total? No: per plane 128*32 w = 4096 w = 256
        // chunks... recompute: 16B chunk = 4 words; 128*32/4 = 1024 chunks
        // per plane; 2 planes = 2048 chunks; 8 per thread.
#pragma unroll
        for (int i = 0; i < 8; i++) {
            int idx = tid + i * 256;
            int p = idx >> 10, rem = idx & 1023;
            int r = rem >> 3, c = rem & 7;
            unsigned dst = smbase + (p * FQ_PL + r * 36 + c * 4) * 4;
            cp16(dst, gq[p] + (size_t)r * 32 + c * 4);
        }
        cp_commit();
    }

    const unsigned* pl[4] = {
        g_kh + (size_t)bh * NNN * 32, g_kl + (size_t)bh * NNN * 32,
        g_vh + (size_t)bh * NNN * 32, g_vl + (size_t)bh * NNN * 32};

    auto prefetch = [&](int kt, int b) {
        // 2048 chunks: 4 planes x 64 rows x 8
#pragma unroll
        for (int i = 0; i < 8; i++) {
            int idx = tid + i * 256;
            int p = idx >> 9, rem = idx & 511;
            int r = rem >> 3, c = rem & 7;
            unsigned dst = smbase
                + (FQ_TOT + b * FV_BUF + p * FV_PL + r * 36 + c * 4) * 4;
            cp16(dst, pl[p] + (size_t)(kt * 64 + r) * 32 + c * 4);
        }
        cp_commit();
    };

    float O[8][4];
    float m0 = -1e30f, m1 = -1e30f, l0 = 0.f, l1 = 0.f;
#pragma unroll
    for (int dt = 0; dt < 8; dt++)
#pragma unroll
        for (int e = 0; e < 4; e++) O[dt][e] = 0.f;

    prefetch(0, 0);

    const unsigned* Qwh = sm + (w * 16) * 36;
    const unsigned* Qwl = Qwh + FQ_PL;

    for (int kt = 0; kt < NNN / 64; kt++) {
        int b = kt & 1;
        if (kt + 1 < NNN / 64) { prefetch(kt + 1, b ^ 1); cp_wait<1>(); }
        else                   { cp_wait<0>(); }
        __syncthreads();

        const unsigned* Kh = sm + FQ_TOT + b * FV_BUF;
        const unsigned* Kl = Kh + FV_PL;
        unsigned vh_base = smbase + (FQ_TOT + b * FV_BUF + 2 * FV_PL) * 4;
        unsigned vl_base = vh_base + FV_PL * 4;

        // S = Q K^T
        float S[8][4];
#pragma unroll
        for (int n = 0; n < 8; n++)
#pragma unroll
            for (int e = 0; e < 4; e++) S[n][e] = 0.f;

#pragma unroll
        for (int kk = 0; kk < 4; kk++) {
            int base = kk * 8 + q4;
            unsigned ah[4], al[4];
            ah[0] = Qwh[g * 36 + base];     ah[1] = Qwh[(g + 8) * 36 + base];
            ah[2] = Qwh[g * 36 + base + 4]; ah[3] = Qwh[(g + 8) * 36 + base + 4];
            al[0] = Qwl[g * 36 + base];     al[1] = Qwl[(g + 8) * 36 + base];
            al[2] = Qwl[g * 36 + base + 4]; al[3] = Qwl[(g + 8) * 36 + base + 4];
#pragma unroll
            for (int nt = 0; nt < 8; nt++) {
                int rw = (nt * 8 + g) * 36;
                unsigned bh0 = Kh[rw + base], bh1 = Kh[rw + base + 4];
                unsigned bl0 = Kl[rw + base], bl1 = Kl[rw + base + 4];
                mma_bf16(S[nt], ah, bh0, bh1);
                mma_bf16(S[nt], ah, bl0, bl1);
                mma_bf16(S[nt], al, bh0, bh1);
            }
        }

        // Online softmax. c0/c1 -> row g ; c2/c3 -> row g+8.
        float mt0 = -1e30f, mt1 = -1e30f;
#pragma unroll
        for (int n = 0; n < 8; n++) {
            mt0 = fmaxf(mt0, fmaxf(S[n][0], S[n][1]));
            mt1 = fmaxf(mt1, fmaxf(S[n][2], S[n][3]));
        }
        mt0 = fmaxf(mt0, __shfl_xor_sync(0xffffffffu, mt0, 1));
        mt0 = fmaxf(mt0, __shfl_xor_sync(0xffffffffu, mt0, 2));
        mt1 = fmaxf(mt1, __shfl_xor_sync(0xffffffffu, mt1, 1));
        mt1 = fmaxf(mt1, __shfl_xor_sync(0xffffffffu, mt1, 2));

        float mn0 = fmaxf(m0, mt0), mn1 = fmaxf(m1, mt1);
        float al0 = __expf(m0 - mn0), al1 = __expf(m1 - mn1);
        m0 = mn0; m1 = mn1;

        float rs0 = 0.f, rs1 = 0.f;
#pragma unroll
        for (int n = 0; n < 8; n++) {
            S[n][0] = __expf(S[n][0] - mn0); rs0 += S[n][0];
            S[n][1] = __expf(S[n][1] - mn0); rs0 += S[n][1];
            S[n][2] = __expf(S[n][2] - mn1); rs1 += S[n][2];
            S[n][3] = __expf(S[n][3] - mn1); rs1 += S[n][3];
        }
        rs0 += __shfl_xor_sync(0xffffffffu, rs0, 1);
        rs0 += __shfl_xor_sync(0xffffffffu, rs0, 2);
        rs1 += __shfl_xor_sync(0xffffffffu, rs1, 1);
        rs1 += __shfl_xor_sync(0xffffffffu, rs1, 2);

        l0 = l0 * al0 + rs0;
        l1 = l1 * al1 + rs1;
#pragma unroll
        for (int dt = 0; dt < 8; dt++) {
            O[dt][0] *= al0; O[dt][1] *= al0;
            O[dt][2] *= al1; O[dt][3] *= al1;
        }

        // O += P @ V  (inline split of P, 8 regs live at a time)
#pragma unroll
        for (int ks = 0; ks < 4; ks++) {
            unsigned ah[4], al_[4];
            split2(S[2*ks][0],   S[2*ks][1],   ah[0], al_[0]);
            split2(S[2*ks][2],   S[2*ks][3],   ah[1], al_[1]);
            split2(S[2*ks+1][0], S[2*ks+1][1], ah[2], al_[2]);
            split2(S[2*ks+1][2], S[2*ks+1][3], ah[3], al_[3]);
            unsigned rowoff = (ks * 16 + (lane & 15)) * 144;
#pragma unroll
            for (int dt = 0; dt < 8; dt++) {
                unsigned vh0, vh1, vl0, vl1;
                ldsm_x2_trans(vh0, vh1, vh_base + rowoff + dt * 16);
                ldsm_x2_trans(vl0, vl1, vl_base + rowoff + dt * 16);
                mma_bf16(O[dt], ah, vh0, vh1);
                mma_bf16(O[dt], ah, vl0, vl1);
                mma_bf16(O[dt], al_, vh0, vh1);
            }
        }
        __syncthreads();   // all warps done with buf b before it's refilled
    }

    // Epilogue -> bf16 hi/lo att planes [M, C] (u32 pairs)
    int b2 = bh / HHH, h = bh % HHH;
    int row0 = qt * 128 + w * 16 + g;
    float inv0 = 1.f / l0, inv1 = 1.f / l1;
    size_t base0 = (size_t)(b2 * NNN + row0) * CW + h * 32;
    size_t base1 = base0 + (size_t)8 * CW;
#pragma unroll
    for (int dt = 0; dt < 8; dt++) {
        unsigned hv, lv;
        split2(O[dt][0] * inv0, O[dt][1] * inv0, hv, lv);
        g_ah[base0 + dt * 4 + q4] = hv; g_al[base0 + dt * 4 + q4] = lv;
        split2(O[dt][2] * inv1, O[dt][3] * inv1, hv, lv);
        g_ah[base1 + dt * 4 + q4] = hv; g_al[base1 + dt * 4 + q4] = lv;
    }
}

// ---------------------------------------------------------------------------
extern "C" void kernel_launch(void* const* d_in, const int* in_sizes, int n_in,
                              void* d_out, int out_size)
{
    const float* x       = (const float*)d_in[0];
    const float* w_qkv   = (const float*)d_in[1];
    const float* q_gamma = (const float*)d_in[2];
    const float* q_beta  = (const float*)d_in[3];
    const float* k_gamma = (const float*)d_in[4];
    const float* k_beta  = (const float*)d_in[5];
    const float* w_proj  = (const float*)d_in[6];
    const float* b_proj  = (const float*)d_in[7];
    float* out = (float*)d_out;

    float* qkv_p;
    unsigned *xh, *xl, *w1h, *w1l, *w2h, *w2l, *ah, *al;
    cudaGetSymbolAddress((void**)&qkv_p, g_qkv);
    cudaGetSymbolAddress((void**)&xh,  g_xh);  cudaGetSymbolAddress((void**)&xl,  g_xl);
    cudaGetSymbolAddress((void**)&w1h, g_w1h); cudaGetSymbolAddress((void**)&w1l, g_w1l);
    cudaGetSymbolAddress((void**)&w2h, g_w2h); cudaGetSymbolAddress((void**)&w2l, g_w2l);
    cudaGetSymbolAddress((void**)&ah,  g_ah);  cudaGetSymbolAddress((void**)&al,  g_al);

    cudaFuncSetAttribute(tgemm_v2,
                         cudaFuncAttributeMaxDynamicSharedMemorySize, GEMM_SMEM);
    cudaFuncSetAttribute(flash_v3,
                         cudaFuncAttributeMaxDynamicSharedMemorySize, FL_SMEM);

    // 0) fp32 -> bf16 hi/lo planes
    split_kernel<<<(MROWS*CW + 255) / 256, 256>>>(x, xh, xl, MROWS*CW);
    split_kernel<<<(CCC*QKVW + 255) / 256, 256>>>(w_qkv, w1h, w1l, CCC*QKVW);
    split_kernel<<<(CCC*CW + 255) / 256, 256>>>(w_proj, w2h, w2l, CCC*CW);

    // 1) QKV GEMM: [8192, 768] @ [768, 2304] -> fp32 g_qkv
    tgemm_v2<<<dim3(QKVC / 128, MROWS / 128), 256, GEMM_SMEM>>>(
        xh, xl, w1h, w1l, qkv_p, QKVC, CCC, nullptr);

    // 2) LayerNorm + split to bf16 hi/lo planes [B*H, N, D]
    ln_kernel<<<(MROWS * 3 * HHH) / 8, 256>>>(q_gamma, q_beta, k_gamma, k_beta);

    // 3) Flash attention (bf16x3, 2 CTAs/SM) -> att planes
    flash_v3<<<dim3(NNN / 128, BH), 256, FL_SMEM>>>();

    // 4) Output projection: [8192, 768] @ [768, 768] + bias -> out
    tgemm_v2<<<dim3(CCC / 128, MROWS / 128), 256, GEMM_SMEM>>>(
        ah, al, w2h, w2l, out, CCC, CCC, b_proj);
}

// round 9
// speedup vs baseline: 3.0115x; 1.0235x over previous
#include <cuda_runtime.h>
#include <cuda_bf16.h>
#include <cstdint>

// Problem constants
#define BB 4
#define NNN 2048
#define CCC 768
#define HHH 12
#define DDD 64
#define MROWS (BB*NNN)     // 8192
#define QKVC (3*CCC)       // 2304
#define BH (BB*HHH)        // 48
#define CW (CCC/2)         // 384 u32 words per row of C
#define QKVW (QKVC/2)      // 1152

// Scratch (device globals — no allocation allowed)
// bf16 hi/lo planes (u32 = packed bf16x2 along the contiguous dim)
__device__ unsigned g_xh[MROWS*CW],  g_xl[MROWS*CW];     // x      [M, C]
__device__ unsigned g_w1h[CCC*QKVW], g_w1l[CCC*QKVW];    // w_qkv  [K, 3C]
__device__ unsigned g_w2h[CCC*CW],   g_w2l[CCC*CW];      // w_proj [K, C]
__device__ unsigned g_qh[BH*NNN*32], g_ql[BH*NNN*32];    // q [B*H,N,D]
__device__ unsigned g_kh[BH*NNN*32], g_kl[BH*NNN*32];
__device__ unsigned g_vh[BH*NNN*32], g_vl[BH*NNN*32];
__device__ unsigned g_ah[MROWS*CW],  g_al[MROWS*CW];     // attn out [M, C]

// ---------------------------------------------------------------------------
// helpers
// ---------------------------------------------------------------------------
__device__ __forceinline__ void mma_bf16(float* d, const unsigned* a,
                                         unsigned b0, unsigned b1)
{
    asm volatile(
        "mma.sync.aligned.m16n8k16.row.col.f32.bf16.bf16.f32 "
        "{%0,%1,%2,%3}, {%4,%5,%6,%7}, {%8,%9}, {%0,%1,%2,%3};\n"
        : "+f"(d[0]), "+f"(d[1]), "+f"(d[2]), "+f"(d[3])
        : "r"(a[0]), "r"(a[1]), "r"(a[2]), "r"(a[3]), "r"(b0), "r"(b1));
}

__device__ __forceinline__ void ldsm_x2_trans(unsigned& r0, unsigned& r1,
                                              unsigned addr)
{
    asm volatile(
        "ldmatrix.sync.aligned.m8n8.x2.trans.shared.b16 {%0,%1}, [%2];"
        : "=r"(r0), "=r"(r1) : "r"(addr));
}

__device__ __forceinline__ void cp16(unsigned dst, const void* src)
{
    asm volatile("cp.async.cg.shared.global [%0], [%1], 16;"
                 :: "r"(dst), "l"(src));
}
__device__ __forceinline__ void cp_commit()
{
    asm volatile("cp.async.commit_group;");
}
template <int N>
__device__ __forceinline__ void cp_wait()
{
    asm volatile("cp.async.wait_group %0;" :: "n"(N));
}

// Split (x,y) into packed bf16x2 hi + lo residual (low 16 bits = x).
__device__ __forceinline__ void split2(float x, float y,
                                       unsigned& h, unsigned& l)
{
    __nv_bfloat162 hb = __floats2bfloat162_rn(x, y);
    float2 hf = __bfloat1622float2(hb);
    __nv_bfloat162 lb = __floats2bfloat162_rn(x - hf.x, y - hf.y);
    h = *reinterpret_cast<unsigned*>(&hb);
    l = *reinterpret_cast<unsigned*>(&lb);
}

// ---------------------------------------------------------------------------
// fp32 -> bf16 hi/lo plane conversion (pair-wise)
// ---------------------------------------------------------------------------
__global__ __launch_bounds__(256) void split_kernel(
    const float* __restrict__ src, unsigned* __restrict__ h,
    unsigned* __restrict__ l, int npairs)
{
    int i = blockIdx.x * 256 + threadIdx.x;
    if (i < npairs) {
        float2 v = reinterpret_cast<const float2*>(src)[i];
        split2(v.x, v.y, h[i], l[i]);
    }
}

// ---------------------------------------------------------------------------
// Shared GEMM smem layout (bf16x3, 128x128x32 block, 8 warps, cp.async
// 2-stage double buffer). A plane: [128][20] u32 (conflict-free b32 loads).
// B plane: [32][68] u32 (272B rows -> conflict-free ldmatrix.x2.trans).
// ---------------------------------------------------------------------------
#define GA_PL 2560              // 128*20
#define GA_BUF (2*GA_PL)        // 5120
#define GB_PL 2176              // 32*68
#define GB_BUF (2*GB_PL)        // 4352
#define GB_BASE (2*GA_BUF)      // 10240
#define GEMM_WORDS (GB_BASE + 2*GB_BUF)   // 18944
#define GEMM_SMEM (GEMM_WORDS*4)          // 75776 B

// Mainloop macro-free duplication: both GEMM kernels share this body shape.

// ---------------------------------------------------------------------------
// tgemm_v2: C[M,N] = A[M,K] @ B[K,N] (+bias), fp32 out.  (proj GEMM)
// ---------------------------------------------------------------------------
__global__ __launch_bounds__(256) void tgemm_v2(
    const unsigned* __restrict__ Ah, const unsigned* __restrict__ Al,
    const unsigned* __restrict__ Bh, const unsigned* __restrict__ Bl,
    float* __restrict__ C, int N, int K, const float* __restrict__ bias)
{
    extern __shared__ unsigned sm[];
    const int Kw = K >> 1, Nw = N >> 1;
    const int nsteps = K / 32;

    int tid = threadIdx.x, w = tid >> 5, lane = tid & 31;
    int g = lane >> 2, q4 = lane & 3;
    int wm = w >> 1, wn = w & 1;

    unsigned smbase = (unsigned)__cvta_generic_to_shared(sm);
    size_t arow0 = (size_t)blockIdx.y * 128;
    int bcol0 = blockIdx.x * 64;          // in u32 pairs

    const unsigned* Apl[2] = {Ah, Al};
    const unsigned* Bpl[2] = {Bh, Bl};

    auto prefetch = [&](int s, int b) {
        int kp0 = s * 16;
#pragma unroll
        for (int i = 0; i < 4; i++) {
            int idx = tid + i * 256;
            int p = idx >> 9, rem = idx & 511;
            int r = rem >> 2, c = rem & 3;
            unsigned dst = smbase + (b * GA_BUF + p * GA_PL + r * 20 + c * 4) * 4;
            cp16(dst, Apl[p] + (arow0 + r) * Kw + kp0 + c * 4);
        }
#pragma unroll
        for (int i = 0; i < 4; i++) {
            int idx = tid + i * 256;
            int p = idx >> 9, rem = idx & 511;
            int r = rem >> 4, c = rem & 15;
            unsigned dst = smbase + (GB_BASE + b * GB_BUF + p * GB_PL
                                     + r * 68 + c * 4) * 4;
            cp16(dst, Bpl[p] + (size_t)(s * 32 + r) * Nw + bcol0 + c * 4);
        }
        cp_commit();
    };

    float acc[2][8][4];
#pragma unroll
    for (int mt = 0; mt < 2; mt++)
#pragma unroll
        for (int nt = 0; nt < 8; nt++)
#pragma unroll
            for (int e = 0; e < 4; e++) acc[mt][nt][e] = 0.f;

    prefetch(0, 0);

    for (int s = 0; s < nsteps; s++) {
        int b = s & 1;
        if (s + 1 < nsteps) { prefetch(s + 1, b ^ 1); cp_wait<1>(); }
        else                { cp_wait<0>(); }
        __syncthreads();

        const unsigned* Ash = sm + b * GA_BUF;
        const unsigned* Asl = Ash + GA_PL;
        unsigned bh_addr = smbase + (GB_BASE + b * GB_BUF) * 4
                           + (lane & 15) * 272;
        unsigned bl_addr = bh_addr + GB_PL * 4;

#pragma unroll
        for (int kc = 0; kc < 2; kc++) {
            unsigned ah[2][4], al[2][4];
#pragma unroll
            for (int mt = 0; mt < 2; mt++) {
                int r0 = (wm * 32 + mt * 16 + g) * 20;
                int r1 = (wm * 32 + mt * 16 + 8 + g) * 20;
                int cidx = kc * 8 + q4;
                ah[mt][0] = Ash[r0 + cidx];     ah[mt][1] = Ash[r1 + cidx];
                ah[mt][2] = Ash[r0 + cidx + 4]; ah[mt][3] = Ash[r1 + cidx + 4];
                al[mt][0] = Asl[r0 + cidx];     al[mt][1] = Asl[r1 + cidx];
                al[mt][2] = Asl[r0 + cidx + 4]; al[mt][3] = Asl[r1 + cidx + 4];
            }
            unsigned rowb = kc * 16 * 272;
#pragma unroll
            for (int nt = 0; nt < 8; nt++) {
                int colb = (wn * 64 + nt * 8) * 2;
                unsigned bh0, bh1, bl0, bl1;
                ldsm_x2_trans(bh0, bh1, bh_addr + rowb + colb);
                ldsm_x2_trans(bl0, bl1, bl_addr + rowb + colb);
#pragma unroll
                for (int mt = 0; mt < 2; mt++) {
                    mma_bf16(acc[mt][nt], ah[mt], bh0, bh1);
                    mma_bf16(acc[mt][nt], ah[mt], bl0, bl1);
                    mma_bf16(acc[mt][nt], al[mt], bh0, bh1);
                }
            }
        }
        __syncthreads();
    }

    int row = blockIdx.y * 128 + wm * 32 + g;
    int colb = blockIdx.x * 128 + wn * 64;
#pragma unroll
    for (int nt = 0; nt < 8; nt++) {
        int col = colb + nt * 8 + 2 * q4;
        float bv0 = 0.f, bv1 = 0.f;
        if (bias) { bv0 = bias[col]; bv1 = bias[col + 1]; }
#pragma unroll
        for (int mt = 0; mt < 2; mt++) {
            float2 u0, u1;
            u0.x = acc[mt][nt][0] + bv0; u0.y = acc[mt][nt][1] + bv1;
            u1.x = acc[mt][nt][2] + bv0; u1.y = acc[mt][nt][3] + bv1;
            *(float2*)(C + (size_t)(row + mt * 16) * N + col) = u0;
            *(float2*)(C + (size_t)(row + mt * 16 + 8) * N + col) = u1;
        }
    }
}

// ---------------------------------------------------------------------------
// tgemm_qkv: QKV GEMM with FUSED LayerNorm + bf16 hi/lo split epilogue.
// Each warp's 64-col patch == exactly one head's D=64 (col blocks 64-aligned,
// 768%128==0), so LN stats are in-register: 16 serial adds + xor-1/2 shuffles
// across the q4 quad give the full 64-col row sum. Writes q/k/v planes
// directly in [B*H, N, D] layout (q gets gamma/beta + 0.125 scale; k gets
// gamma/beta; v is a plain split copy). No fp32 qkv buffer, no ln_kernel.
// ---------------------------------------------------------------------------
__global__ __launch_bounds__(256) void tgemm_qkv(
    const unsigned* __restrict__ Ah, const unsigned* __restrict__ Al,
    const unsigned* __restrict__ Bh, const unsigned* __restrict__ Bl,
    const float* __restrict__ qg, const float* __restrict__ qb,
    const float* __restrict__ kg, const float* __restrict__ kb)
{
    extern __shared__ unsigned sm[];
    const int N = QKVC, K = CCC;
    const int Kw = K >> 1, Nw = N >> 1;
    const int nsteps = K / 32;

    int tid = threadIdx.x, w = tid >> 5, lane = tid & 31;
    int g = lane >> 2, q4 = lane & 3;
    int wm = w >> 1, wn = w & 1;

    unsigned smbase = (unsigned)__cvta_generic_to_shared(sm);
    size_t arow0 = (size_t)blockIdx.y * 128;
    int bcol0 = blockIdx.x * 64;

    const unsigned* Apl[2] = {Ah, Al};
    const unsigned* Bpl[2] = {Bh, Bl};

    auto prefetch = [&](int s, int b) {
        int kp0 = s * 16;
#pragma unroll
        for (int i = 0; i < 4; i++) {
            int idx = tid + i * 256;
            int p = idx >> 9, rem = idx & 511;
            int r = rem >> 2, c = rem & 3;
            unsigned dst = smbase + (b * GA_BUF + p * GA_PL + r * 20 + c * 4) * 4;
            cp16(dst, Apl[p] + (arow0 + r) * Kw + kp0 + c * 4);
        }
#pragma unroll
        for (int i = 0; i < 4; i++) {
            int idx = tid + i * 256;
            int p = idx >> 9, rem = idx & 511;
            int r = rem >> 4, c = rem & 15;
            unsigned dst = smbase + (GB_BASE + b * GB_BUF + p * GB_PL
                                     + r * 68 + c * 4) * 4;
            cp16(dst, Bpl[p] + (size_t)(s * 32 + r) * Nw + bcol0 + c * 4);
        }
        cp_commit();
    };

    float acc[2][8][4];
#pragma unroll
    for (int mt = 0; mt < 2; mt++)
#pragma unroll
        for (int nt = 0; nt < 8; nt++)
#pragma unroll
            for (int e = 0; e < 4; e++) acc[mt][nt][e] = 0.f;

    prefetch(0, 0);

    for (int s = 0; s < nsteps; s++) {
        int b = s & 1;
        if (s + 1 < nsteps) { prefetch(s + 1, b ^ 1); cp_wait<1>(); }
        else                { cp_wait<0>(); }
        __syncthreads();

        const unsigned* Ash = sm + b * GA_BUF;
        const unsigned* Asl = Ash + GA_PL;
        unsigned bh_addr = smbase + (GB_BASE + b * GB_BUF) * 4
                           + (lane & 15) * 272;
        unsigned bl_addr = bh_addr + GB_PL * 4;

#pragma unroll
        for (int kc = 0; kc < 2; kc++) {
            unsigned ah[2][4], al[2][4];
#pragma unroll
            for (int mt = 0; mt < 2; mt++) {
                int r0 = (wm * 32 + mt * 16 + g) * 20;
                int r1 = (wm * 32 + mt * 16 + 8 + g) * 20;
                int cidx = kc * 8 + q4;
                ah[mt][0] = Ash[r0 + cidx];     ah[mt][1] = Ash[r1 + cidx];
                ah[mt][2] = Ash[r0 + cidx + 4]; ah[mt][3] = Ash[r1 + cidx + 4];
                al[mt][0] = Asl[r0 + cidx];     al[mt][1] = Asl[r1 + cidx];
                al[mt][2] = Asl[r0 + cidx + 4]; al[mt][3] = Asl[r1 + cidx + 4];
            }
            unsigned rowb = kc * 16 * 272;
#pragma unroll
            for (int nt = 0; nt < 8; nt++) {
                int colb = (wn * 64 + nt * 8) * 2;
                unsigned bh0, bh1, bl0, bl1;
                ldsm_x2_trans(bh0, bh1, bh_addr + rowb + colb);
                ldsm_x2_trans(bl0, bl1, bl_addr + rowb + colb);
#pragma unroll
                for (int mt = 0; mt < 2; mt++) {
                    mma_bf16(acc[mt][nt], ah[mt], bh0, bh1);
                    mma_bf16(acc[mt][nt], ah[mt], bl0, bl1);
                    mma_bf16(acc[mt][nt], al[mt], bh0, bh1);
                }
            }
        }
        __syncthreads();
    }

    // ---- fused LN + split epilogue ----
    int colblk = blockIdx.x * 128 + wn * 64;    // 64-aligned head boundary
    int s = colblk / CCC;                       // 0=q, 1=k, 2=v
    int hh = (colblk % CCC) / DDD;              // head index
    const float* gw = (s == 0) ? qg : kg;
    const float* be = (s == 0) ? qb : kb;
    float sc = (s == 0) ? 0.125f : 1.f;         // D^-0.5 folded into q
    unsigned* dh = (s == 0) ? g_qh : (s == 1) ? g_kh : g_vh;
    unsigned* dl = (s == 0) ? g_ql : (s == 1) ? g_kl : g_vl;

#pragma unroll
    for (int mt = 0; mt < 2; mt++) {
#pragma unroll
        for (int half = 0; half < 2; half++) {
            int e0 = 2 * half;
            int m = blockIdx.y * 128 + wm * 32 + mt * 16 + half * 8 + g;
            size_t base = (((size_t)((m >> 11) * HHH + hh)) * NNN
                           + (m & (NNN - 1))) * 32;
            if (s < 2) {
                float sum = 0.f, sq = 0.f;
#pragma unroll
                for (int nt = 0; nt < 8; nt++) {
                    float a0 = acc[mt][nt][e0], a1 = acc[mt][nt][e0 + 1];
                    sum += a0 + a1; sq += a0 * a0 + a1 * a1;
                }
                sum += __shfl_xor_sync(0xffffffffu, sum, 1);
                sum += __shfl_xor_sync(0xffffffffu, sum, 2);
                sq  += __shfl_xor_sync(0xffffffffu, sq, 1);
                sq  += __shfl_xor_sync(0xffffffffu, sq, 2);
                float mean = sum * (1.f / 64.f);
                float var  = sq * (1.f / 64.f) - mean * mean;
                float inv  = rsqrtf(var + 1e-5f);
#pragma unroll
                for (int nt = 0; nt < 8; nt++) {
                    int d = nt * 8 + 2 * q4;
                    float2 gv = *(const float2*)(gw + d);
                    float2 bv = *(const float2*)(be + d);
                    float y0 = ((acc[mt][nt][e0]     - mean) * inv * gv.x + bv.x) * sc;
                    float y1 = ((acc[mt][nt][e0 + 1] - mean) * inv * gv.y + bv.y) * sc;
                    unsigned hv, lv; split2(y0, y1, hv, lv);
                    dh[base + nt * 4 + q4] = hv;
                    dl[base + nt * 4 + q4] = lv;
                }
            } else {
#pragma unroll
                for (int nt = 0; nt < 8; nt++) {
                    unsigned hv, lv;
                    split2(acc[mt][nt][e0], acc[mt][nt][e0 + 1], hv, lv);
                    dh[base + nt * 4 + q4] = hv;
                    dl[base + nt * 4 + q4] = lv;
                }
            }
        }
    }
}

// ---------------------------------------------------------------------------
// Flash attention v3 (unchanged from round 6): bf16x3, 2 CTAs/SM.
// ---------------------------------------------------------------------------
#define FQ_PL 4608
#define FQ_TOT (2*FQ_PL)
#define FV_PL 2304
#define FV_BUF (4*FV_PL)
#define FL_WORDS (FQ_TOT + 2*FV_BUF)
#define FL_SMEM (FL_WORDS*4)

__global__ __launch_bounds__(256, 2) void flash_v3()
{
    extern __shared__ unsigned sm[];
    unsigned smbase = (unsigned)__cvta_generic_to_shared(sm);

    int bh = blockIdx.y, qt = blockIdx.x;
    int tid = threadIdx.x, w = tid >> 5, lane = tid & 31;
    int g = lane >> 2, q4 = lane & 3;

    // Q fill (once): 2 planes x 1024 16B-chunks each
    {
        const unsigned* gq[2] = {
            g_qh + ((size_t)bh * NNN + qt * 128) * 32,
            g_ql + ((size_t)bh * NNN + qt * 128) * 32};
#pragma unroll
        for (int i = 0; i < 8; i++) {
            int idx = tid + i * 256;
            int p = idx >> 10, rem = idx & 1023;
            int r = rem >> 3, c = rem & 7;
            unsigned dst = smbase + (p * FQ_PL + r * 36 + c * 4) * 4;
            cp16(dst, gq[p] + (size_t)r * 32 + c * 4);
        }
        cp_commit();
    }

    const unsigned* pl[4] = {
        g_kh + (size_t)bh * NNN * 32, g_kl + (size_t)bh * NNN * 32,
        g_vh + (size_t)bh * NNN * 32, g_vl + (size_t)bh * NNN * 32};

    auto prefetch = [&](int kt, int b) {
#pragma unroll
        for (int i = 0; i < 8; i++) {
            int idx = tid + i * 256;
            int p = idx >> 9, rem = idx & 511;
            int r = rem >> 3, c = rem & 7;
            unsigned dst = smbase
                + (FQ_TOT + b * FV_BUF + p * FV_PL + r * 36 + c * 4) * 4;
            cp16(dst, pl[p] + (size_t)(kt * 64 + r) * 32 + c * 4);
        }
        cp_commit();
    };

    float O[8][4];
    float m0 = -1e30f, m1 = -1e30f, l0 = 0.f, l1 = 0.f;
#pragma unroll
    for (int dt = 0; dt < 8; dt++)
#pragma unroll
        for (int e = 0; e < 4; e++) O[dt][e] = 0.f;

    prefetch(0, 0);

    const unsigned* Qwh = sm + (w * 16) * 36;
    const unsigned* Qwl = Qwh + FQ_PL;

    for (int kt = 0; kt < NNN / 64; kt++) {
        int b = kt & 1;
        if (kt + 1 < NNN / 64) { prefetch(kt + 1, b ^ 1); cp_wait<1>(); }
        else                   { cp_wait<0>(); }
        __syncthreads();

        const unsigned* Kh = sm + FQ_TOT + b * FV_BUF;
        const unsigned* Kl = Kh + FV_PL;
        unsigned vh_base = smbase + (FQ_TOT + b * FV_BUF + 2 * FV_PL) * 4;
        unsigned vl_base = vh_base + FV_PL * 4;

        float S[8][4];
#pragma unroll
        for (int n = 0; n < 8; n++)
#pragma unroll
            for (int e = 0; e < 4; e++) S[n][e] = 0.f;

#pragma unroll
        for (int kk = 0; kk < 4; kk++) {
            int base = kk * 8 + q4;
            unsigned ah[4], al[4];
            ah[0] = Qwh[g * 36 + base];     ah[1] = Qwh[(g + 8) * 36 + base];
            ah[2] = Qwh[g * 36 + base + 4]; ah[3] = Qwh[(g + 8) * 36 + base + 4];
            al[0] = Qwl[g * 36 + base];     al[1] = Qwl[(g + 8) * 36 + base];
            al[2] = Qwl[g * 36 + base + 4]; al[3] = Qwl[(g + 8) * 36 + base + 4];
#pragma unroll
            for (int nt = 0; nt < 8; nt++) {
                int rw = (nt * 8 + g) * 36;
                unsigned bh0 = Kh[rw + base], bh1 = Kh[rw + base + 4];
                unsigned bl0 = Kl[rw + base], bl1 = Kl[rw + base + 4];
                mma_bf16(S[nt], ah, bh0, bh1);
                mma_bf16(S[nt], ah, bl0, bl1);
                mma_bf16(S[nt], al, bh0, bh1);
            }
        }

        float mt0 = -1e30f, mt1 = -1e30f;
#pragma unroll
        for (int n = 0; n < 8; n++) {
            mt0 = fmaxf(mt0, fmaxf(S[n][0], S[n][1]));
            mt1 = fmaxf(mt1, fmaxf(S[n][2], S[n][3]));
        }
        mt0 = fmaxf(mt0, __shfl_xor_sync(0xffffffffu, mt0, 1));
        mt0 = fmaxf(mt0, __shfl_xor_sync(0xffffffffu, mt0, 2));
        mt1 = fmaxf(mt1, __shfl_xor_sync(0xffffffffu, mt1, 1));
        mt1 = fmaxf(mt1, __shfl_xor_sync(0xffffffffu, mt1, 2));

        float mn0 = fmaxf(m0, mt0), mn1 = fmaxf(m1, mt1);
        float al0 = __expf(m0 - mn0), al1 = __expf(m1 - mn1);
        m0 = mn0; m1 = mn1;

        float rs0 = 0.f, rs1 = 0.f;
#pragma unroll
        for (int n = 0; n < 8; n++) {
            S[n][0] = __expf(S[n][0] - mn0); rs0 += S[n][0];
            S[n][1] = __expf(S[n][1] - mn0); rs0 += S[n][1];
            S[n][2] = __expf(S[n][2] - mn1); rs1 += S[n][2];
            S[n][3] = __expf(S[n][3] - mn1); rs1 += S[n][3];
        }
        rs0 += __shfl_xor_sync(0xffffffffu, rs0, 1);
        rs0 += __shfl_xor_sync(0xffffffffu, rs0, 2);
        rs1 += __shfl_xor_sync(0xffffffffu, rs1, 1);
        rs1 += __shfl_xor_sync(0xffffffffu, rs1, 2);

        l0 = l0 * al0 + rs0;
        l1 = l1 * al1 + rs1;
#pragma unroll
        for (int dt = 0; dt < 8; dt++) {
            O[dt][0] *= al0; O[dt][1] *= al0;
            O[dt][2] *= al1; O[dt][3] *= al1;
        }

#pragma unroll
        for (int ks = 0; ks < 4; ks++) {
            unsigned ah[4], al_[4];
            split2(S[2*ks][0],   S[2*ks][1],   ah[0], al_[0]);
            split2(S[2*ks][2],   S[2*ks][3],   ah[1], al_[1]);
            split2(S[2*ks+1][0], S[2*ks+1][1], ah[2], al_[2]);
            split2(S[2*ks+1][2], S[2*ks+1][3], ah[3], al_[3]);
            unsigned rowoff = (ks * 16 + (lane & 15)) * 144;
#pragma unroll
            for (int dt = 0; dt < 8; dt++) {
                unsigned vh0, vh1, vl0, vl1;
                ldsm_x2_trans(vh0, vh1, vh_base + rowoff + dt * 16);
                ldsm_x2_trans(vl0, vl1, vl_base + rowoff + dt * 16);
                mma_bf16(O[dt], ah, vh0, vh1);
                mma_bf16(O[dt], ah, vl0, vl1);
                mma_bf16(O[dt], al_, vh0, vh1);
            }
        }
        __syncthreads();
    }

    int b2 = bh / HHH, h = bh % HHH;
    int row0 = qt * 128 + w * 16 + g;
    float inv0 = 1.f / l0, inv1 = 1.f / l1;
    size_t base0 = (size_t)(b2 * NNN + row0) * CW + h * 32;
    size_t base1 = base0 + (size_t)8 * CW;
#pragma unroll
    for (int dt = 0; dt < 8; dt++) {
        unsigned hv, lv;
        split2(O[dt][0] * inv0, O[dt][1] * inv0, hv, lv);
        g_ah[base0 + dt * 4 + q4] = hv; g_al[base0 + dt * 4 + q4] = lv;
        split2(O[dt][2] * inv1, O[dt][3] * inv1, hv, lv);
        g_ah[base1 + dt * 4 + q4] = hv; g_al[base1 + dt * 4 + q4] = lv;
    }
}

// ---------------------------------------------------------------------------
extern "C" void kernel_launch(void* const* d_in, const int* in_sizes, int n_in,
                              void* d_out, int out_size)
{
    const float* x       = (const float*)d_in[0];
    const float* w_qkv   = (const float*)d_in[1];
    const float* q_gamma = (const float*)d_in[2];
    const float* q_beta  = (const float*)d_in[3];
    const float* k_gamma = (const float*)d_in[4];
    const float* k_beta  = (const float*)d_in[5];
    const float* w_proj  = (const float*)d_in[6];
    const float* b_proj  = (const float*)d_in[7];
    float* out = (float*)d_out;

    unsigned *xh, *xl, *w1h, *w1l, *w2h, *w2l, *ah, *al;
    cudaGetSymbolAddress((void**)&xh,  g_xh);  cudaGetSymbolAddress((void**)&xl,  g_xl);
    cudaGetSymbolAddress((void**)&w1h, g_w1h); cudaGetSymbolAddress((void**)&w1l, g_w1l);
    cudaGetSymbolAddress((void**)&w2h, g_w2h); cudaGetSymbolAddress((void**)&w2l, g_w2l);
    cudaGetSymbolAddress((void**)&ah,  g_ah);  cudaGetSymbolAddress((void**)&al,  g_al);

    cudaFuncSetAttribute(tgemm_v2,
                         cudaFuncAttributeMaxDynamicSharedMemorySize, GEMM_SMEM);
    cudaFuncSetAttribute(tgemm_qkv,
                         cudaFuncAttributeMaxDynamicSharedMemorySize, GEMM_SMEM);
    cudaFuncSetAttribute(flash_v3,
                         cudaFuncAttributeMaxDynamicSharedMemorySize, FL_SMEM);

    // 0) fp32 -> bf16 hi/lo planes
    split_kernel<<<(MROWS*CW + 255) / 256, 256>>>(x, xh, xl, MROWS*CW);
    split_kernel<<<(CCC*QKVW + 255) / 256, 256>>>(w_qkv, w1h, w1l, CCC*QKVW);
    split_kernel<<<(CCC*CW + 255) / 256, 256>>>(w_proj, w2h, w2l, CCC*CW);

    // 1) QKV GEMM with fused LayerNorm + split -> q/k/v planes [B*H, N, D]
    tgemm_qkv<<<dim3(QKVC / 128, MROWS / 128), 256, GEMM_SMEM>>>(
        xh, xl, w1h, w1l, q_gamma, q_beta, k_gamma, k_beta);

    // 2) Flash attention (bf16x3, 2 CTAs/SM) -> att planes
    flash_v3<<<dim3(NNN / 128, BH), 256, FL_SMEM>>>();

    // 3) Output projection: [8192, 768] @ [768, 768] + bias -> out
    tgemm_v2<<<dim3(CCC / 128, MROWS / 128), 256, GEMM_SMEM>>>(
        ah, al, w2h, w2l, out, CCC, CCC, b_proj);
}